// round 4
// baseline (speedup 1.0000x reference)
#include <cuda_runtime.h>
#include <cstdint>

#define NB 32
#define NT 4096
#define ND 256
#define NK 1024
#define TS_INT 4104        // token stride of intermediate activation buffers

// ---------------- scratch (static device globals; no allocation) ----------------
__device__ float  g_bufA[(size_t)NB * TS_INT * ND];
__device__ float  g_bufB[(size_t)NB * TS_INT * ND];
__device__ float  g_whi[(size_t)ND * 1024];
__device__ float  g_wlo[(size_t)ND * 1024];
__device__ double g_sum[ND];
__device__ double g_sumsq[ND];
__device__ float  g_scale[ND];
__device__ float  g_shift[ND];
__device__ float  g_cnorm[NK];
__device__ float  g_cnt[NK];
__device__ float  g_sumcur[(size_t)NK * ND];
__device__ float  g_n;

// ---------------- helpers --------------------------------------------------------
__device__ __forceinline__ uint32_t smem_u32(const void* p) {
    uint32_t a;
    asm("{ .reg .u64 t; cvta.to.shared.u64 t, %1; cvt.u32.u64 %0, t; }" : "=r"(a) : "l"(p));
    return a;
}
__device__ __forceinline__ float tf32r(float x) {
    float r;
    asm("cvt.rna.tf32.f32 %0, %1;" : "=f"(r) : "f"(x));
    return r;
}
__device__ __forceinline__ uint32_t swz(uint32_t off) { return off ^ ((off >> 3) & 0x70); }

__device__ __forceinline__ void ldm_x4(uint32_t& r0, uint32_t& r1, uint32_t& r2, uint32_t& r3, uint32_t a) {
    asm volatile("ldmatrix.sync.aligned.m8n8.x4.shared.b16 {%0,%1,%2,%3}, [%4];"
                 : "=r"(r0), "=r"(r1), "=r"(r2), "=r"(r3) : "r"(a));
}
__device__ __forceinline__ void ldm_x2(uint32_t& r0, uint32_t& r1, uint32_t a) {
    asm volatile("ldmatrix.sync.aligned.m8n8.x2.shared.b16 {%0,%1}, [%2];"
                 : "=r"(r0), "=r"(r1) : "r"(a));
}
__device__ __forceinline__ void mma8(float* c, const uint32_t* a, const uint32_t* b) {
    asm volatile("mma.sync.aligned.m16n8k8.row.col.f32.tf32.tf32.f32 "
        "{%0,%1,%2,%3}, {%4,%5,%6,%7}, {%8,%9}, {%0,%1,%2,%3};"
        : "+f"(c[0]), "+f"(c[1]), "+f"(c[2]), "+f"(c[3])
        : "r"(a[0]), "r"(a[1]), "r"(a[2]), "r"(a[3]), "r"(b[0]), "r"(b[1]));
}

// smem layout per stage: A_hi[128][32] | A_lo | B_hi[128][32] | B_lo  (SW128 rows)
#define O_ALO 16384
#define O_BHI 32768
#define O_BLO 49152
#define STAGE 65536
#define O_STAT (2 * STAGE)                 // double ssum[128], ssq[128]
#define SMEM_MMA (O_STAT + 2048)

// ---------------- weight split prep (per layer) ---------------------------------
__global__ void wsplit_kernel(const float* __restrict__ w)
{
    int i = blockIdx.x * 256 + threadIdx.x;          // 65536 float4s
    float4 v = *(const float4*)&w[(size_t)i * 4];
    float4 hi, lo;
    hi.x = tf32r(v.x); lo.x = tf32r(v.x - hi.x);
    hi.y = tf32r(v.y); lo.y = tf32r(v.y - hi.y);
    hi.z = tf32r(v.z); lo.z = tf32r(v.z - hi.z);
    hi.w = tf32r(v.w); lo.w = tf32r(v.w - hi.w);
    *(float4*)&g_whi[(size_t)i * 4] = hi;
    *(float4*)&g_wlo[(size_t)i * 4] = lo;
}

// ============ conv D->D as mma.sync tf32 3x-split GEMM ==========================
// C[128 oc][128 tok] = sum_k W[oc][k] * im2col(X)[tok][k], K=1024 = 32 chunks
__global__ __launch_bounds__(256, 1) void convmma_kernel(
    const float* __restrict__ in, const float* __restrict__ bias,
    float* __restrict__ out, int Lin, int Lout, int pad, int tstride, int do_stats)
{
    extern __shared__ __align__(128) char smem[];
    const int tid = threadIdx.x;
    const int wid = tid >> 5, lane = tid & 31;
    const int b = blockIdx.z, oc0 = blockIdx.y * 128, t0 = blockIdx.x * 128;
    const int ocw = (wid & 1) * 64;          // warp oc base (within CTA tile)
    const int tokw = (wid >> 1) * 32;        // warp tok base

    const uint32_t sb = smem_u32(smem);
    const float* xb = in + (size_t)b * TS_INT * ND;

    // fragment base offsets (within a stage, relative to A_hi / B_hi blocks)
    uint32_t abase[4], bbase[4];
    {
        int ar = ocw + (lane & 7) + ((lane >> 3) & 1) * 8;
        int aq = (lane >> 4) & 1;
#pragma unroll
        for (int mt = 0; mt < 4; mt++) {
            int r = ar + mt * 16;
            abase[mt] = (uint32_t)(r * 128 + ((aq * 16) ^ ((r & 7) << 4)));
        }
        int br = tokw + (lane & 7);
        int bq = (lane >> 3) & 1;
#pragma unroll
        for (int nt = 0; nt < 4; nt++) {
            int r = br + nt * 8;
            bbase[nt] = (uint32_t)(r * 128 + ((bq * 16) ^ ((r & 7) << 4)));
        }
    }

    float C[4][4][4];
#pragma unroll
    for (int mt = 0; mt < 4; mt++)
#pragma unroll
        for (int nt = 0; nt < 4; nt++)
#pragma unroll
            for (int q = 0; q < 4; q++) C[mt][nt][q] = 0.f;

    const int cl = lane >> 2, kk = lane & 3;

    for (int cc = 0; cc < 32; cc++) {
        char* st = smem + (cc & 1) * STAGE;
        const uint32_t su = sb + (cc & 1) * STAGE;

        // ---- A producer: pre-split weights, SW128 rows of 32 floats ----------
        {
            const float* whp = g_whi + (size_t)oc0 * 1024 + cc * 32;
            const float* wlp = g_wlo + (size_t)oc0 * 1024 + cc * 32;
            for (int idx = tid; idx < 2048; idx += 256) {
                int r = idx >> 3, ql = idx & 7;
                int rr = r & 127;
                const float* src = ((r < 128) ? whp : wlp) + (size_t)rr * 1024 + ql * 4;
                uint32_t off = ((r < 128) ? 0u : (uint32_t)O_ALO) + swz((uint32_t)(rr * 128 + ql * 16));
                *(float4*)(st + off) = *(const float4*)src;
            }
        }
        // ---- B producer: im2col + BN + ReLU + tf32 split ---------------------
        {
            const int ch0 = cc * 8;
            const int ch = ch0 + cl;
            const float sc = g_scale[ch], sh = g_shift[ch];
            for (int j = wid; j < 131; j += 8) {
                int ti = t0 - pad + j;
                float v = 0.f;
                if ((unsigned)ti < (unsigned)Lin) {
                    float raw = xb[(size_t)ti * ND + ch];
                    v = fmaxf(fmaf(raw, sc, sh), 0.f);
                }
                float hi = tf32r(v);
                float lo = tf32r(v - hi);
                int n = j - kk;
                if ((unsigned)n < 128u) {
                    uint32_t sw = swz((uint32_t)(n * 128 + lane * 4));
                    *(float*)(st + O_BHI + sw) = hi;
                    *(float*)(st + O_BLO + sw) = lo;
                }
            }
        }
        __syncthreads();

        // ---- mma over this chunk (K=32 -> 4 k-steps of 8) --------------------
#pragma unroll
        for (int ks = 0; ks < 4; ks++) {
            uint32_t bh[4][2], bl[4][2];
#pragma unroll
            for (int nt = 0; nt < 4; nt++) {
                uint32_t ad = su + O_BHI + (bbase[nt] ^ (uint32_t)(ks << 5));
                ldm_x2(bh[nt][0], bh[nt][1], ad);
                ldm_x2(bl[nt][0], bl[nt][1], ad + (O_BLO - O_BHI));
            }
#pragma unroll
            for (int mt = 0; mt < 4; mt++) {
                uint32_t ah[4], al[4];
                uint32_t ad = su + (abase[mt] ^ (uint32_t)(ks << 5));
                ldm_x4(ah[0], ah[1], ah[2], ah[3], ad);
                ldm_x4(al[0], al[1], al[2], al[3], ad + O_ALO);
#pragma unroll
                for (int nt = 0; nt < 4; nt++) {
                    mma8(C[mt][nt], ah, bh[nt]);
                    mma8(C[mt][nt], ah, bl[nt]);
                    mma8(C[mt][nt], al, bh[nt]);
                }
            }
        }
        // no sync here: stage s is re-written at cc+2, fenced by cc+1's barrier
    }
    __syncthreads();

    // ---- epilogue: bias + BN stats + smem transpose + coalesced store ----------
    double* ssumS = (double*)(smem + O_STAT);
    double* ssqS  = (double*)(smem + O_STAT + 1024);
    if (tid < 128) { ssumS[tid] = 0.0; ssqS[tid] = 0.0; }
    float* eb = (float*)smem;                 // [128 tok][132 oc]
    __syncthreads();

#pragma unroll
    for (int mt = 0; mt < 4; mt++) {
#pragma unroll
        for (int h = 0; h < 2; h++) {
            int ocl = ocw + mt * 16 + (lane >> 2) + h * 8;
            float bv = bias[oc0 + ocl];
            double s = 0.0, q = 0.0;
#pragma unroll
            for (int nt = 0; nt < 4; nt++) {
#pragma unroll
                for (int p = 0; p < 2; p++) {
                    int n = tokw + nt * 8 + (lane & 3) * 2 + p;
                    float v = C[mt][nt][h * 2 + p] + bv;
                    eb[n * 132 + ocl] = v;
                    if (do_stats && (t0 + n < Lout)) { double d = (double)v; s += d; q += d * d; }
                }
            }
            if (do_stats) { atomicAdd(&ssumS[ocl], s); atomicAdd(&ssqS[ocl], q); }
        }
    }
    __syncthreads();

    for (int idx = tid; idx < 4096; idx += 256) {
        int r = idx >> 5, ql = idx & 31;
        if (t0 + r < Lout)
            *(float4*)&out[((size_t)b * tstride + t0 + r) * ND + oc0 + ql * 4] =
                *(float4*)&eb[r * 132 + ql * 4];
    }
    if (do_stats && tid < 128) {
        atomicAdd(&g_sum[oc0 + tid], ssumS[tid]);
        atomicAdd(&g_sumsq[oc0 + tid], ssqS[tid]);
    }
}

// ---------------- layer 1: conv 12 -> 256, k=4, pad=2 (scalar; tiny K) ----------
__global__ __launch_bounds__(256) void conv1_kernel(
    const float* __restrict__ x, const float* __restrict__ w,
    const float* __restrict__ bias, float* __restrict__ out)
{
    __shared__ float in_s[12][68];
    __shared__ float w_s[64][49];
    __shared__ float o_s[64][65];
    __shared__ double ssum[64], ssq[64];

    const int tid = threadIdx.x;
    const int b = blockIdx.z, oc0 = blockIdx.y * 64, t0 = blockIdx.x * 64;
    const int ocl = tid & 63, tg = tid >> 6, tbase = tg * 16;
    const int Lout = 4097;

    for (int idx = tid; idx < 12 * 67; idx += 256) {
        int j = idx / 12, c = idx - j * 12;
        int ip = t0 - 2 + j;
        in_s[c][j] = ((unsigned)ip < 4096u) ? x[((size_t)b * NT + ip) * 12 + c] : 0.f;
    }
    for (int idx = tid; idx < 64 * 48; idx += 256) {
        int oc = idx / 48, r = idx - oc * 48;
        w_s[oc][r] = w[(size_t)(oc0 + oc) * 48 + r];
    }
    __syncthreads();

    float acc[16];
#pragma unroll
    for (int u = 0; u < 16; u++) acc[u] = 0.f;
#pragma unroll
    for (int c = 0; c < 12; c++) {
        float v[19];
#pragma unroll
        for (int u = 0; u < 19; u++) v[u] = in_s[c][tbase + u];
        float w0 = w_s[ocl][c * 4 + 0], w1 = w_s[ocl][c * 4 + 1];
        float w2 = w_s[ocl][c * 4 + 2], w3 = w_s[ocl][c * 4 + 3];
#pragma unroll
        for (int u = 0; u < 16; u++)
            acc[u] = fmaf(w3, v[u + 3], fmaf(w2, v[u + 2], fmaf(w1, v[u + 1], fmaf(w0, v[u], acc[u]))));
    }
    const float bv = bias[oc0 + ocl];
#pragma unroll
    for (int u = 0; u < 16; u++) acc[u] += bv;

    {
        double s = 0.0, q = 0.0;
#pragma unroll
        for (int u = 0; u < 16; u++)
            if (t0 + tbase + u < Lout) { double a = (double)acc[u]; s += a; q += a * a; }
        __syncthreads();
        if (tid < 64) { ssum[tid] = 0.0; ssq[tid] = 0.0; }
        __syncthreads();
        atomicAdd(&ssum[ocl], s);
        atomicAdd(&ssq[ocl], q);
        __syncthreads();
        if (tid < 64) {
            atomicAdd(&g_sum[oc0 + tid], ssum[tid]);
            atomicAdd(&g_sumsq[oc0 + tid], ssq[tid]);
        }
    }

    __syncthreads();
#pragma unroll
    for (int u = 0; u < 16; u++) o_s[ocl][tbase + u] = acc[u];
    __syncthreads();
    float* ob = out + ((size_t)b * TS_INT + t0) * ND + oc0;
    for (int idx = tid; idx < 4096; idx += 256) {
        int t = idx >> 6, oc = idx & 63;
        if (t0 + t < Lout) ob[(size_t)t * ND + oc] = o_s[oc][t];
    }
}

// ---------------- BN stats -> scale/shift for next layer; resets stats ----------
__global__ void scaleshift_kernel(const float* __restrict__ g, const float* __restrict__ be, double N)
{
    int c = threadIdx.x;
    double m = g_sum[c] / N;
    double var = g_sumsq[c] / N - m * m;
    double r = 1.0 / sqrt(var + 1e-5);
    double sc = (double)g[c] * r;
    g_scale[c] = (float)sc;
    g_shift[c] = (float)((double)be[c] - m * sc);
    g_sum[c] = 0.0;
    g_sumsq[c] = 0.0;
}

// ---------------- ||codebook_k||^2 ----------------------------------------------
__global__ void cnorm_kernel(const float* __restrict__ cb)
{
    int gw = (blockIdx.x * 256 + threadIdx.x) >> 5;
    int lane = threadIdx.x & 31;
    float s = 0.f;
    const float* row = cb + (size_t)gw * ND;
    for (int d = lane; d < ND; d += 32) { float v = row[d]; s = fmaf(v, v, s); }
#pragma unroll
    for (int off = 16; off; off >>= 1) s += __shfl_xor_sync(0xffffffffu, s, off);
    if (lane == 0) g_cnorm[gw] = s;
}

// ---------------- VQ: argmin + z_q write + counts + segment sums ----------------
__global__ __launch_bounds__(256) void vq_kernel(
    const float* __restrict__ ze, const float* __restrict__ cb, float* __restrict__ zq)
{
    __shared__ float z_s[64][17];
    __shared__ float c_s[128][17];
    __shared__ int sbest[64];

    const int tid = threadIdx.x;
    const int tok0 = blockIdx.x * 64;
    const int tokg = tid >> 4;
    const int codeg = tid & 15;

    float bval[4];
    int bidx[4];
#pragma unroll
    for (int i = 0; i < 4; i++) { bval[i] = 1e30f; bidx[i] = 0x7fffffff; }

    for (int ct = 0; ct < NK; ct += 128) {
        float acc[4][8];
#pragma unroll
        for (int i = 0; i < 4; i++)
#pragma unroll
            for (int j = 0; j < 8; j++) acc[i][j] = 0.f;

        for (int d0 = 0; d0 < ND; d0 += 16) {
            __syncthreads();
            for (int idx = tid; idx < 1024; idx += 256) {
                int r = idx >> 4, dj = idx & 15;
                z_s[r][dj] = ze[(size_t)(tok0 + r) * ND + d0 + dj];
            }
            for (int idx = tid; idx < 2048; idx += 256) {
                int r = idx >> 4, dj = idx & 15;
                c_s[r][dj] = cb[(size_t)(ct + r) * ND + d0 + dj];
            }
            __syncthreads();
#pragma unroll
            for (int dj = 0; dj < 16; dj++) {
                float zr[4], cr[8];
#pragma unroll
                for (int i = 0; i < 4; i++) zr[i] = z_s[tokg * 4 + i][dj];
#pragma unroll
                for (int j = 0; j < 8; j++) cr[j] = c_s[codeg + 16 * j][dj];
#pragma unroll
                for (int i = 0; i < 4; i++)
#pragma unroll
                    for (int j = 0; j < 8; j++)
                        acc[i][j] = fmaf(zr[i], cr[j], acc[i][j]);
            }
        }
#pragma unroll
        for (int j = 0; j < 8; j++) {
            int code = ct + codeg + 16 * j;
            float cn = g_cnorm[code];
#pragma unroll
            for (int i = 0; i < 4; i++) {
                float s = fmaf(-2.f, acc[i][j], cn);
                if (s < bval[i] || (s == bval[i] && code < bidx[i])) { bval[i] = s; bidx[i] = code; }
            }
        }
    }
#pragma unroll
    for (int off = 8; off >= 1; off >>= 1) {
#pragma unroll
        for (int i = 0; i < 4; i++) {
            float ov = __shfl_xor_sync(0xffffffffu, bval[i], off);
            int oi = __shfl_xor_sync(0xffffffffu, bidx[i], off);
            if (ov < bval[i] || (ov == bval[i] && oi < bidx[i])) { bval[i] = ov; bidx[i] = oi; }
        }
    }
    if (codeg == 0) {
#pragma unroll
        for (int i = 0; i < 4; i++) sbest[tokg * 4 + i] = bidx[i];
    }
    __syncthreads();
    if (tid < 64) atomicAdd(&g_cnt[sbest[tid]], 1.0f);
    for (int e = tid; e < 64 * ND; e += 256) {
        int r = e >> 8, d = e & 255;
        int code = sbest[r];
        size_t gz = (size_t)(tok0 + r) * ND + d;
        float zev = ze[gz];
        float cbv = cb[(size_t)code * ND + d];
        zq[gz] = zev + (cbv - zev);
        atomicAdd(&g_sumcur[(size_t)code * ND + d], zev);
    }
}

// ---------------- EMA epilogue ---------------------------------------------------
__global__ void ema1_kernel(const float* __restrict__ ecs, float* __restrict__ necs)
{
    __shared__ float red[1024];
    int k = threadIdx.x;
    float ne = ecs[k] * 0.99f + 0.01f * g_cnt[k];
    necs[k] = ne;
    g_cnt[k] = 0.f;
    red[k] = ne;
    __syncthreads();
    for (int off = 512; off; off >>= 1) {
        if (k < off) red[k] += red[k + off];
        __syncthreads();
    }
    if (k == 0) g_n = red[0];
}

__global__ void ema2_kernel(const float* __restrict__ ema_w, const float* __restrict__ necs,
                            float* __restrict__ ncb)
{
    int k = blockIdx.x, d = threadIdx.x;
    float n = g_n;
    float smoothed = (necs[k] + 1e-5f) / (n + 1024.f * 1e-5f) * n;
    size_t idx = (size_t)k * ND + d;
    float nw = ema_w[idx] * 0.99f + 0.01f * g_sumcur[idx];
    ncb[idx] = nw / smoothed;
    g_sumcur[idx] = 0.f;
}

// ---------------- host launcher ---------------------------------------------------
extern "C" void kernel_launch(void* const* d_in, const int* in_sizes, int n_in,
                              void* d_out, int out_size)
{
    const float* X = (const float*)d_in[0];
    const float *W[6], *Bi[6], *G[5], *Be[5];

    bool sig = (in_sizes[3] == 256);
    if (!sig) {
        for (int i = 0; i < 6; i++) { W[i] = (const float*)d_in[1 + 2 * i]; Bi[i] = (const float*)d_in[2 + 2 * i]; }
        for (int i = 0; i < 5; i++) { G[i] = (const float*)d_in[13 + 2 * i]; Be[i] = (const float*)d_in[14 + 2 * i]; }
    } else {
        for (int i = 0; i < 5; i++) {
            W[i]  = (const float*)d_in[1 + 4 * i];
            Bi[i] = (const float*)d_in[2 + 4 * i];
            G[i]  = (const float*)d_in[3 + 4 * i];
            Be[i] = (const float*)d_in[4 + 4 * i];
        }
        W[5] = (const float*)d_in[21];
        Bi[5] = (const float*)d_in[22];
    }
    const float* codebook = (const float*)d_in[23];
    const float* ema_w    = (const float*)d_in[24];
    const float* ecs      = (const float*)d_in[25];

    float* out  = (float*)d_out;
    float* ze   = out;
    float* zq   = out + (size_t)33554432;
    float* ncb  = out + (size_t)67108864;
    float* necs = out + (size_t)67371008;

    float *bufA = nullptr, *bufB = nullptr;
    cudaGetSymbolAddress((void**)&bufA, g_bufA);
    cudaGetSymbolAddress((void**)&bufB, g_bufB);

    cudaFuncSetAttribute(convmma_kernel, cudaFuncAttributeMaxDynamicSharedMemorySize, SMEM_MMA);

    dim3 blk(256);
    // L1 (scalar, K=48): x -> A[t][c], Lout=4097, stats
    conv1_kernel<<<dim3(65, 4, 32), blk>>>(X, W[0], Bi[0], bufA);
    scaleshift_kernel<<<1, 256>>>(G[0], Be[0], (double)(32.0 * 4097.0));
    // L2: A(4097) -> B(4096), pad 1
    wsplit_kernel<<<256, 256>>>(W[1]);
    convmma_kernel<<<dim3(32, 2, 32), blk, SMEM_MMA>>>(bufA, Bi[1], bufB, 4097, 4096, 1, TS_INT, 1);
    scaleshift_kernel<<<1, 256>>>(G[1], Be[1], (double)(32.0 * 4096.0));
    // L3: B(4096) -> A(4097), pad 2
    wsplit_kernel<<<256, 256>>>(W[2]);
    convmma_kernel<<<dim3(33, 2, 32), blk, SMEM_MMA>>>(bufB, Bi[2], bufA, 4096, 4097, 2, TS_INT, 1);
    scaleshift_kernel<<<1, 256>>>(G[2], Be[2], (double)(32.0 * 4097.0));
    // L4: A(4097) -> B(4096), pad 1
    wsplit_kernel<<<256, 256>>>(W[3]);
    convmma_kernel<<<dim3(32, 2, 32), blk, SMEM_MMA>>>(bufA, Bi[3], bufB, 4097, 4096, 1, TS_INT, 1);
    scaleshift_kernel<<<1, 256>>>(G[3], Be[3], (double)(32.0 * 4096.0));
    // L5: B(4096) -> A(4097), pad 2
    wsplit_kernel<<<256, 256>>>(W[4]);
    convmma_kernel<<<dim3(33, 2, 32), blk, SMEM_MMA>>>(bufB, Bi[4], bufA, 4096, 4097, 2, TS_INT, 1);
    scaleshift_kernel<<<1, 256>>>(G[4], Be[4], (double)(32.0 * 4097.0));
    // L6: A(4097) -> z_e [b][t][d] (stride 4096), pad 1, no stats
    wsplit_kernel<<<256, 256>>>(W[5]);
    convmma_kernel<<<dim3(32, 2, 32), blk, SMEM_MMA>>>(bufA, Bi[5], ze, 4097, 4096, 1, 4096, 0);

    cnorm_kernel<<<128, 256>>>(codebook);
    vq_kernel<<<2048, 256>>>(ze, codebook, zq);
    ema1_kernel<<<1, 1024>>>(ecs, necs);
    ema2_kernel<<<1024, 256>>>(ema_w, necs, ncb);
}

// round 5
// speedup vs baseline: 1.5208x; 1.5208x over previous
#include <cuda_runtime.h>
#include <cstdint>

#define NB 32
#define NT 4096
#define ND 256
#define NK 1024
#define TS_INT 4104        // token stride of intermediate activation buffers

// ---------------- scratch (static device globals; no allocation) ----------------
__device__ float  g_bufA[(size_t)NB * TS_INT * ND];
__device__ float  g_bufB[(size_t)NB * TS_INT * ND];
__device__ float  g_whi[(size_t)ND * 1024];     // permuted: [oc][chunk][kk][ch&7]
__device__ float  g_wlo[(size_t)ND * 1024];
__device__ double g_sum[ND];
__device__ double g_sumsq[ND];
__device__ float  g_scale[ND];
__device__ float  g_shift[ND];
__device__ float  g_cnorm[NK];
__device__ float  g_cnt[NK];
__device__ float  g_sumcur[(size_t)NK * ND];
__device__ float  g_n;

// ---------------- helpers --------------------------------------------------------
__device__ __forceinline__ uint32_t smem_u32(const void* p) {
    uint32_t a;
    asm("{ .reg .u64 t; cvta.to.shared.u64 t, %1; cvt.u32.u64 %0, t; }" : "=r"(a) : "l"(p));
    return a;
}
__device__ __forceinline__ float tf32r(float x) {
    float r;
    asm("cvt.rna.tf32.f32 %0, %1;" : "=f"(r) : "f"(x));
    return r;
}
__device__ __forceinline__ uint32_t swz(uint32_t off) { return off ^ ((off >> 3) & 0x70); }

__device__ __forceinline__ void ldm_x4(uint32_t& r0, uint32_t& r1, uint32_t& r2, uint32_t& r3, uint32_t a) {
    asm volatile("ldmatrix.sync.aligned.m8n8.x4.shared.b16 {%0,%1,%2,%3}, [%4];"
                 : "=r"(r0), "=r"(r1), "=r"(r2), "=r"(r3) : "r"(a));
}
__device__ __forceinline__ void ldm_x2(uint32_t& r0, uint32_t& r1, uint32_t a) {
    asm volatile("ldmatrix.sync.aligned.m8n8.x2.shared.b16 {%0,%1}, [%2];"
                 : "=r"(r0), "=r"(r1) : "r"(a));
}
__device__ __forceinline__ void mma8(float* c, const uint32_t* a, const uint32_t* b) {
    asm volatile("mma.sync.aligned.m16n8k8.row.col.f32.tf32.tf32.f32 "
        "{%0,%1,%2,%3}, {%4,%5,%6,%7}, {%8,%9}, {%0,%1,%2,%3};"
        : "+f"(c[0]), "+f"(c[1]), "+f"(c[2]), "+f"(c[3])
        : "r"(a[0]), "r"(a[1]), "r"(a[2]), "r"(a[3]), "r"(b[0]), "r"(b[1]));
}
#define CP_ASYNC16(dst, src) asm volatile("cp.async.cg.shared.global [%0], [%1], 16;" :: "r"(dst), "l"(src))
#define CP_COMMIT()  asm volatile("cp.async.commit_group;" ::: "memory")
#define CP_WAIT0()   asm volatile("cp.async.wait_group 0;" ::: "memory")

// smem stage: A_hi[128 rows x 128B] | A_lo | B_hi[136 rows x 32B] | B_lo
#define O_ALO 16384
#define O_BHI 32768
#define O_BLO (32768 + 4608)
#define STAGE 41984                          // 41 KB, 1024-aligned
#define O_STAT (2 * STAGE)
#define SMEM_MMA (O_STAT + 2048)

// ---------------- weight split + permute prep (per layer) -----------------------
// in: w[oc][ch][kk]  ->  out[oc][ch>>3][kk][ch&7], tf32 hi/lo split
__global__ void wsplit_kernel(const float* __restrict__ w)
{
    int i = blockIdx.x * 256 + threadIdx.x;      // 65536 = (oc, ch)
    int oc = i >> 8, ch = i & 255;
    float4 v = *(const float4*)&w[(size_t)oc * 1024 + ch * 4];
    size_t base = (size_t)oc * 1024 + (ch >> 3) * 32 + (ch & 7);
#pragma unroll
    for (int kk = 0; kk < 4; kk++) {
        float x = (&v.x)[kk];
        float hi = tf32r(x);
        g_whi[base + kk * 8] = hi;
        g_wlo[base + kk * 8] = tf32r(x - hi);
    }
}

// ============ conv D->D: pipelined mma.sync tf32 3x-split, tap-shifted B ========
// C[128 oc][128 tok]; K = 32 chunks of (8 ch x 4 taps). B tile has NO im2col dup:
// fragment for tap kk reads token rows shifted by kk (per-lane ldmatrix addrs).
__global__ __launch_bounds__(256, 1) void convmma_kernel(
    const float* __restrict__ in, const float* __restrict__ bias,
    float* __restrict__ out, int Lin, int Lout, int pad, int tstride, int do_stats)
{
    extern __shared__ __align__(1024) char smem[];
    const int tid = threadIdx.x;
    const int wid = tid >> 5, lane = tid & 31;
    const int b = blockIdx.z, oc0 = blockIdx.y * 128, t0 = blockIdx.x * 128;
    const int ocw = (wid & 1) * 64;
    const int tokw = (wid >> 1) * 32;

    const uint32_t sb = smem_u32(smem);
    const float* xb = in + (size_t)b * TS_INT * ND;

    // A fragment bases (within stage, SW128 rows of 128B) — validated scheme
    uint32_t abase[4];
    {
        int ar = ocw + (lane & 7) + ((lane >> 3) & 1) * 8;
        int aq = (lane >> 4) & 1;
#pragma unroll
        for (int mt = 0; mt < 4; mt++) {
            int r = ar + mt * 16;
            abase[mt] = (uint32_t)(r * 128 + ((aq * 16) ^ ((r & 7) << 4)));
        }
    }
    // B per-lane ldmatrix row base (32B swizzled rows)
    const int lb = lane & 15;
    const int rb0 = tokw + (lb & 7);
    const uint32_t sg = (uint32_t)(((lb >> 3) & 1) << 4);

    float C[4][4][4];
#pragma unroll
    for (int mt = 0; mt < 4; mt++)
#pragma unroll
        for (int nt = 0; nt < 4; nt++)
#pragma unroll
            for (int q = 0; q < 4; q++) C[mt][nt][q] = 0.f;

    // ---- B prefetch state: thread -> (token j = tid>>1, seg h = tid&1) ---------
    const int jj = tid >> 1, hh = tid & 1;
    const int jx = 128 + (tid >> 1);             // extra rows 128..130 for tid<6
    float4 bpre0, bpre1, spre, hpre;

    // ---- prologue: stage 0 -----------------------------------------------------
    {
        const float* whp = g_whi + (size_t)oc0 * 1024;
        const float* wlp = g_wlo + (size_t)oc0 * 1024;
#pragma unroll
        for (int it = 0; it < 8; it++) {
            int idx = tid + it * 256, r = idx >> 3, ql = idx & 7, rr = r & 127;
            const float* src = ((r < 128) ? whp : wlp) + (size_t)rr * 1024 + ql * 4;
            uint32_t dst = sb + ((r < 128) ? 0u : (uint32_t)O_ALO) + swz((uint32_t)(rr * 128 + ql * 16));
            CP_ASYNC16(dst, src);
        }
        CP_COMMIT();
        int ti = t0 - pad + jj;
        bpre0 = ((unsigned)ti < (unsigned)Lin) ? *(const float4*)&xb[(size_t)ti * ND + hh * 4]
                                               : make_float4(0.f, 0.f, 0.f, 0.f);
        if ((unsigned)ti >= (unsigned)Lin) bpre0.x = __int_as_float(0x7fffffff);  // marker unused; keep zero
        bpre0 = ((unsigned)ti < (unsigned)Lin) ? *(const float4*)&xb[(size_t)ti * ND + hh * 4]
                                               : make_float4(0.f, 0.f, 0.f, 0.f);
        if (tid < 6) {
            int t2 = t0 - pad + jx;
            bpre1 = ((unsigned)t2 < (unsigned)Lin) ? *(const float4*)&xb[(size_t)t2 * ND + hh * 4]
                                                   : make_float4(0.f, 0.f, 0.f, 0.f);
        }
        spre = *(const float4*)&g_scale[hh * 4];
        hpre = *(const float4*)&g_shift[hh * 4];
    }

    for (int cc = 0; cc < 32; cc++) {
        const uint32_t su = sb + (cc & 1) * STAGE;
        char* st = smem + (cc & 1) * STAGE;

        CP_WAIT0();
        // ---- STS B from prefetch regs (BN+ReLU+split at store time) -----------
        {
            int ti = t0 - pad + jj;
            bool ok = (unsigned)ti < (unsigned)Lin;
            float4 hi4, lo4;
#pragma unroll
            for (int q = 0; q < 4; q++) {
                float v = ok ? fmaxf(fmaf((&bpre0.x)[q], (&spre.x)[q], (&hpre.x)[q]), 0.f) : 0.f;
                float h = tf32r(v);
                (&hi4.x)[q] = h; (&lo4.x)[q] = tf32r(v - h);
            }
            uint32_t byte = (uint32_t)(jj * 32 + hh * 16) ^ ((uint32_t)(jj & 4) << 2);
            *(float4*)(st + O_BHI + byte) = hi4;
            *(float4*)(st + O_BLO + byte) = lo4;
            if (tid < 6) {
                int t2 = t0 - pad + jx;
                bool ok2 = (unsigned)t2 < (unsigned)Lin;
                float4 hi2, lo2;
#pragma unroll
                for (int q = 0; q < 4; q++) {
                    float v = ok2 ? fmaxf(fmaf((&bpre1.x)[q], (&spre.x)[q], (&hpre.x)[q]), 0.f) : 0.f;
                    float h = tf32r(v);
                    (&hi2.x)[q] = h; (&lo2.x)[q] = tf32r(v - h);
                }
                uint32_t byte2 = (uint32_t)(jx * 32 + hh * 16) ^ ((uint32_t)(jx & 4) << 2);
                *(float4*)(st + O_BHI + byte2) = hi2;
                *(float4*)(st + O_BLO + byte2) = lo2;
            }
        }
        __syncthreads();

        // ---- prefetch chunk cc+1 (A via cp.async, B via regs) ------------------
        if (cc + 1 < 32) {
            const float* whp = g_whi + (size_t)oc0 * 1024 + (cc + 1) * 32;
            const float* wlp = g_wlo + (size_t)oc0 * 1024 + (cc + 1) * 32;
            uint32_t sd = sb + ((cc + 1) & 1) * STAGE;
#pragma unroll
            for (int it = 0; it < 8; it++) {
                int idx = tid + it * 256, r = idx >> 3, ql = idx & 7, rr = r & 127;
                const float* src = ((r < 128) ? whp : wlp) + (size_t)rr * 1024 + ql * 4;
                uint32_t dst = sd + ((r < 128) ? 0u : (uint32_t)O_ALO) + swz((uint32_t)(rr * 128 + ql * 16));
                CP_ASYNC16(dst, src);
            }
            CP_COMMIT();
            const int ch0 = (cc + 1) * 8;
            int ti = t0 - pad + jj;
            bpre0 = ((unsigned)ti < (unsigned)Lin) ? *(const float4*)&xb[(size_t)ti * ND + ch0 + hh * 4]
                                                   : make_float4(0.f, 0.f, 0.f, 0.f);
            if (tid < 6) {
                int t2 = t0 - pad + jx;
                bpre1 = ((unsigned)t2 < (unsigned)Lin) ? *(const float4*)&xb[(size_t)t2 * ND + ch0 + hh * 4]
                                                       : make_float4(0.f, 0.f, 0.f, 0.f);
            }
            spre = *(const float4*)&g_scale[ch0 + hh * 4];
            hpre = *(const float4*)&g_shift[ch0 + hh * 4];
        }

        // ---- mma on chunk cc: 4 k-steps (= taps), tap kk shifts B rows by kk ---
#pragma unroll
        for (int ks = 0; ks < 4; ks++) {
            uint32_t bh[4][2], bl[4][2];
#pragma unroll
            for (int nt = 0; nt < 4; nt++) {
                int r = rb0 + nt * 8 + ks;
                uint32_t byte = ((uint32_t)(r * 32) + sg) ^ ((uint32_t)(r & 4) << 2);
                uint32_t ad = su + O_BHI + byte;
                ldm_x2(bh[nt][0], bh[nt][1], ad);
                ldm_x2(bl[nt][0], bl[nt][1], ad + (O_BLO - O_BHI));
            }
#pragma unroll
            for (int mt = 0; mt < 4; mt++) {
                uint32_t ah[4], al[4];
                uint32_t ad = su + (abase[mt] ^ (uint32_t)(ks << 5));
                ldm_x4(ah[0], ah[1], ah[2], ah[3], ad);
                ldm_x4(al[0], al[1], al[2], al[3], ad + O_ALO);
#pragma unroll
                for (int nt = 0; nt < 4; nt++) mma8(C[mt][nt], ah, bh[nt]);
#pragma unroll
                for (int nt = 0; nt < 4; nt++) mma8(C[mt][nt], ah, bl[nt]);
#pragma unroll
                for (int nt = 0; nt < 4; nt++) mma8(C[mt][nt], al, bh[nt]);
            }
        }
        __syncthreads();
    }

    // ---- epilogue: bias + BN stats + smem transpose + coalesced store ----------
    double* ssumS = (double*)(smem + O_STAT);
    double* ssqS  = (double*)(smem + O_STAT + 1024);
    if (tid < 128) { ssumS[tid] = 0.0; ssqS[tid] = 0.0; }
    float* eb = (float*)smem;                 // [128 tok][132 oc]
    __syncthreads();

#pragma unroll
    for (int mt = 0; mt < 4; mt++) {
#pragma unroll
        for (int h = 0; h < 2; h++) {
            int ocl = ocw + mt * 16 + (lane >> 2) + h * 8;
            float bv = bias[oc0 + ocl];
            double s = 0.0, q = 0.0;
#pragma unroll
            for (int nt = 0; nt < 4; nt++) {
#pragma unroll
                for (int p = 0; p < 2; p++) {
                    int n = tokw + nt * 8 + (lane & 3) * 2 + p;
                    float v = C[mt][nt][h * 2 + p] + bv;
                    eb[n * 132 + ocl] = v;
                    if (do_stats && (t0 + n < Lout)) { double d = (double)v; s += d; q += d * d; }
                }
            }
            if (do_stats) { atomicAdd(&ssumS[ocl], s); atomicAdd(&ssqS[ocl], q); }
        }
    }
    __syncthreads();

    for (int idx = tid; idx < 4096; idx += 256) {
        int r = idx >> 5, ql = idx & 31;
        if (t0 + r < Lout)
            *(float4*)&out[((size_t)b * tstride + t0 + r) * ND + oc0 + ql * 4] =
                *(float4*)&eb[r * 132 + ql * 4];
    }
    if (do_stats && tid < 128) {
        atomicAdd(&g_sum[oc0 + tid], ssumS[tid]);
        atomicAdd(&g_sumsq[oc0 + tid], ssqS[tid]);
    }
}

// ---------------- layer 1: conv 12 -> 256, k=4, pad=2 (scalar; tiny K) ----------
__global__ __launch_bounds__(256) void conv1_kernel(
    const float* __restrict__ x, const float* __restrict__ w,
    const float* __restrict__ bias, float* __restrict__ out)
{
    __shared__ float in_s[12][68];
    __shared__ float w_s[64][49];
    __shared__ float o_s[64][65];
    __shared__ double ssum[64], ssq[64];

    const int tid = threadIdx.x;
    const int b = blockIdx.z, oc0 = blockIdx.y * 64, t0 = blockIdx.x * 64;
    const int ocl = tid & 63, tg = tid >> 6, tbase = tg * 16;
    const int Lout = 4097;

    for (int idx = tid; idx < 12 * 67; idx += 256) {
        int j = idx / 12, c = idx - j * 12;
        int ip = t0 - 2 + j;
        in_s[c][j] = ((unsigned)ip < 4096u) ? x[((size_t)b * NT + ip) * 12 + c] : 0.f;
    }
    for (int idx = tid; idx < 64 * 48; idx += 256) {
        int oc = idx / 48, r = idx - oc * 48;
        w_s[oc][r] = w[(size_t)(oc0 + oc) * 48 + r];
    }
    __syncthreads();

    float acc[16];
#pragma unroll
    for (int u = 0; u < 16; u++) acc[u] = 0.f;
#pragma unroll
    for (int c = 0; c < 12; c++) {
        float v[19];
#pragma unroll
        for (int u = 0; u < 19; u++) v[u] = in_s[c][tbase + u];
        float w0 = w_s[ocl][c * 4 + 0], w1 = w_s[ocl][c * 4 + 1];
        float w2 = w_s[ocl][c * 4 + 2], w3 = w_s[ocl][c * 4 + 3];
#pragma unroll
        for (int u = 0; u < 16; u++)
            acc[u] = fmaf(w3, v[u + 3], fmaf(w2, v[u + 2], fmaf(w1, v[u + 1], fmaf(w0, v[u], acc[u]))));
    }
    const float bv = bias[oc0 + ocl];
#pragma unroll
    for (int u = 0; u < 16; u++) acc[u] += bv;

    {
        double s = 0.0, q = 0.0;
#pragma unroll
        for (int u = 0; u < 16; u++)
            if (t0 + tbase + u < Lout) { double a = (double)acc[u]; s += a; q += a * a; }
        __syncthreads();
        if (tid < 64) { ssum[tid] = 0.0; ssq[tid] = 0.0; }
        __syncthreads();
        atomicAdd(&ssum[ocl], s);
        atomicAdd(&ssq[ocl], q);
        __syncthreads();
        if (tid < 64) {
            atomicAdd(&g_sum[oc0 + tid], ssum[tid]);
            atomicAdd(&g_sumsq[oc0 + tid], ssq[tid]);
        }
    }

    __syncthreads();
#pragma unroll
    for (int u = 0; u < 16; u++) o_s[ocl][tbase + u] = acc[u];
    __syncthreads();
    float* ob = out + ((size_t)b * TS_INT + t0) * ND + oc0;
    for (int idx = tid; idx < 4096; idx += 256) {
        int t = idx >> 6, oc = idx & 63;
        if (t0 + t < Lout) ob[(size_t)t * ND + oc] = o_s[oc][t];
    }
}

// ---------------- BN stats -> scale/shift for next layer; resets stats ----------
__global__ void scaleshift_kernel(const float* __restrict__ g, const float* __restrict__ be, double N)
{
    int c = threadIdx.x;
    double m = g_sum[c] / N;
    double var = g_sumsq[c] / N - m * m;
    double r = 1.0 / sqrt(var + 1e-5);
    double sc = (double)g[c] * r;
    g_scale[c] = (float)sc;
    g_shift[c] = (float)((double)be[c] - m * sc);
    g_sum[c] = 0.0;
    g_sumsq[c] = 0.0;
}

// ---------------- ||codebook_k||^2 ----------------------------------------------
__global__ void cnorm_kernel(const float* __restrict__ cb)
{
    int gw = (blockIdx.x * 256 + threadIdx.x) >> 5;
    int lane = threadIdx.x & 31;
    float s = 0.f;
    const float* row = cb + (size_t)gw * ND;
    for (int d = lane; d < ND; d += 32) { float v = row[d]; s = fmaf(v, v, s); }
#pragma unroll
    for (int off = 16; off; off >>= 1) s += __shfl_xor_sync(0xffffffffu, s, off);
    if (lane == 0) g_cnorm[gw] = s;
}

// ---------------- VQ: argmin + z_q write + counts + segment sums ----------------
__global__ __launch_bounds__(256) void vq_kernel(
    const float* __restrict__ ze, const float* __restrict__ cb, float* __restrict__ zq)
{
    __shared__ float z_s[64][17];
    __shared__ float c_s[128][17];
    __shared__ int sbest[64];

    const int tid = threadIdx.x;
    const int tok0 = blockIdx.x * 64;
    const int tokg = tid >> 4;
    const int codeg = tid & 15;

    float bval[4];
    int bidx[4];
#pragma unroll
    for (int i = 0; i < 4; i++) { bval[i] = 1e30f; bidx[i] = 0x7fffffff; }

    for (int ct = 0; ct < NK; ct += 128) {
        float acc[4][8];
#pragma unroll
        for (int i = 0; i < 4; i++)
#pragma unroll
            for (int j = 0; j < 8; j++) acc[i][j] = 0.f;

        for (int d0 = 0; d0 < ND; d0 += 16) {
            __syncthreads();
            for (int idx = tid; idx < 1024; idx += 256) {
                int r = idx >> 4, dj = idx & 15;
                z_s[r][dj] = ze[(size_t)(tok0 + r) * ND + d0 + dj];
            }
            for (int idx = tid; idx < 2048; idx += 256) {
                int r = idx >> 4, dj = idx & 15;
                c_s[r][dj] = cb[(size_t)(ct + r) * ND + d0 + dj];
            }
            __syncthreads();
#pragma unroll
            for (int dj = 0; dj < 16; dj++) {
                float zr[4], cr[8];
#pragma unroll
                for (int i = 0; i < 4; i++) zr[i] = z_s[tokg * 4 + i][dj];
#pragma unroll
                for (int j = 0; j < 8; j++) cr[j] = c_s[codeg + 16 * j][dj];
#pragma unroll
                for (int i = 0; i < 4; i++)
#pragma unroll
                    for (int j = 0; j < 8; j++)
                        acc[i][j] = fmaf(zr[i], cr[j], acc[i][j]);
            }
        }
#pragma unroll
        for (int j = 0; j < 8; j++) {
            int code = ct + codeg + 16 * j;
            float cn = g_cnorm[code];
#pragma unroll
            for (int i = 0; i < 4; i++) {
                float s = fmaf(-2.f, acc[i][j], cn);
                if (s < bval[i] || (s == bval[i] && code < bidx[i])) { bval[i] = s; bidx[i] = code; }
            }
        }
    }
#pragma unroll
    for (int off = 8; off >= 1; off >>= 1) {
#pragma unroll
        for (int i = 0; i < 4; i++) {
            float ov = __shfl_xor_sync(0xffffffffu, bval[i], off);
            int oi = __shfl_xor_sync(0xffffffffu, bidx[i], off);
            if (ov < bval[i] || (ov == bval[i] && oi < bidx[i])) { bval[i] = ov; bidx[i] = oi; }
        }
    }
    if (codeg == 0) {
#pragma unroll
        for (int i = 0; i < 4; i++) sbest[tokg * 4 + i] = bidx[i];
    }
    __syncthreads();
    if (tid < 64) atomicAdd(&g_cnt[sbest[tid]], 1.0f);
    for (int e = tid; e < 64 * ND; e += 256) {
        int r = e >> 8, d = e & 255;
        int code = sbest[r];
        size_t gz = (size_t)(tok0 + r) * ND + d;
        float zev = ze[gz];
        float cbv = cb[(size_t)code * ND + d];
        zq[gz] = zev + (cbv - zev);
        atomicAdd(&g_sumcur[(size_t)code * ND + d], zev);
    }
}

// ---------------- EMA epilogue ---------------------------------------------------
__global__ void ema1_kernel(const float* __restrict__ ecs, float* __restrict__ necs)
{
    __shared__ float red[1024];
    int k = threadIdx.x;
    float ne = ecs[k] * 0.99f + 0.01f * g_cnt[k];
    necs[k] = ne;
    g_cnt[k] = 0.f;
    red[k] = ne;
    __syncthreads();
    for (int off = 512; off; off >>= 1) {
        if (k < off) red[k] += red[k + off];
        __syncthreads();
    }
    if (k == 0) g_n = red[0];
}

__global__ void ema2_kernel(const float* __restrict__ ema_w, const float* __restrict__ necs,
                            float* __restrict__ ncb)
{
    int k = blockIdx.x, d = threadIdx.x;
    float n = g_n;
    float smoothed = (necs[k] + 1e-5f) / (n + 1024.f * 1e-5f) * n;
    size_t idx = (size_t)k * ND + d;
    float nw = ema_w[idx] * 0.99f + 0.01f * g_sumcur[idx];
    ncb[idx] = nw / smoothed;
    g_sumcur[idx] = 0.f;
}

// ---------------- host launcher ---------------------------------------------------
extern "C" void kernel_launch(void* const* d_in, const int* in_sizes, int n_in,
                              void* d_out, int out_size)
{
    const float* X = (const float*)d_in[0];
    const float *W[6], *Bi[6], *G[5], *Be[5];

    bool sig = (in_sizes[3] == 256);
    if (!sig) {
        for (int i = 0; i < 6; i++) { W[i] = (const float*)d_in[1 + 2 * i]; Bi[i] = (const float*)d_in[2 + 2 * i]; }
        for (int i = 0; i < 5; i++) { G[i] = (const float*)d_in[13 + 2 * i]; Be[i] = (const float*)d_in[14 + 2 * i]; }
    } else {
        for (int i = 0; i < 5; i++) {
            W[i]  = (const float*)d_in[1 + 4 * i];
            Bi[i] = (const float*)d_in[2 + 4 * i];
            G[i]  = (const float*)d_in[3 + 4 * i];
            Be[i] = (const float*)d_in[4 + 4 * i];
        }
        W[5] = (const float*)d_in[21];
        Bi[5] = (const float*)d_in[22];
    }
    const float* codebook = (const float*)d_in[23];
    const float* ema_w    = (const float*)d_in[24];
    const float* ecs      = (const float*)d_in[25];

    float* out  = (float*)d_out;
    float* ze   = out;
    float* zq   = out + (size_t)33554432;
    float* ncb  = out + (size_t)67108864;
    float* necs = out + (size_t)67371008;

    float *bufA = nullptr, *bufB = nullptr;
    cudaGetSymbolAddress((void**)&bufA, g_bufA);
    cudaGetSymbolAddress((void**)&bufB, g_bufB);

    cudaFuncSetAttribute(convmma_kernel, cudaFuncAttributeMaxDynamicSharedMemorySize, SMEM_MMA);

    dim3 blk(256);
    conv1_kernel<<<dim3(65, 4, 32), blk>>>(X, W[0], Bi[0], bufA);
    scaleshift_kernel<<<1, 256>>>(G[0], Be[0], (double)(32.0 * 4097.0));
    wsplit_kernel<<<256, 256>>>(W[1]);
    convmma_kernel<<<dim3(32, 2, 32), blk, SMEM_MMA>>>(bufA, Bi[1], bufB, 4097, 4096, 1, TS_INT, 1);
    scaleshift_kernel<<<1, 256>>>(G[1], Be[1], (double)(32.0 * 4096.0));
    wsplit_kernel<<<256, 256>>>(W[2]);
    convmma_kernel<<<dim3(33, 2, 32), blk, SMEM_MMA>>>(bufB, Bi[2], bufA, 4096, 4097, 2, TS_INT, 1);
    scaleshift_kernel<<<1, 256>>>(G[2], Be[2], (double)(32.0 * 4097.0));
    wsplit_kernel<<<256, 256>>>(W[3]);
    convmma_kernel<<<dim3(32, 2, 32), blk, SMEM_MMA>>>(bufA, Bi[3], bufB, 4097, 4096, 1, TS_INT, 1);
    scaleshift_kernel<<<1, 256>>>(G[3], Be[3], (double)(32.0 * 4096.0));
    wsplit_kernel<<<256, 256>>>(W[4]);
    convmma_kernel<<<dim3(33, 2, 32), blk, SMEM_MMA>>>(bufB, Bi[4], bufA, 4096, 4097, 2, TS_INT, 1);
    scaleshift_kernel<<<1, 256>>>(G[4], Be[4], (double)(32.0 * 4097.0));
    wsplit_kernel<<<256, 256>>>(W[5]);
    convmma_kernel<<<dim3(32, 2, 32), blk, SMEM_MMA>>>(bufA, Bi[5], ze, 4097, 4096, 1, 4096, 0);

    cnorm_kernel<<<128, 256>>>(codebook);
    vq_kernel<<<2048, 256>>>(ze, codebook, zq);
    ema1_kernel<<<1, 1024>>>(ecs, necs);
    ema2_kernel<<<1024, 256>>>(ema_w, necs, ncb);
}

// round 6
// speedup vs baseline: 1.5219x; 1.0007x over previous
#include <cuda_runtime.h>
#include <cstdint>

#define NB 32
#define NT 4096
#define ND 256
#define NK 1024
#define TS_INT 4104        // token stride of intermediate activation buffers

// ---------------- scratch (static device globals; no allocation) ----------------
__device__ float  g_bufA[(size_t)NB * TS_INT * ND];
__device__ float  g_bufB[(size_t)NB * TS_INT * ND];
__device__ float  g_whi[(size_t)ND * 1024];     // permuted: [oc][chunk][kk][ch&7]
__device__ float  g_wlo[(size_t)ND * 1024];
__device__ double g_sum[ND];
__device__ double g_sumsq[ND];
__device__ float  g_scale[ND];
__device__ float  g_shift[ND];
__device__ float  g_cnorm[NK];
__device__ float  g_cnt[NK];
__device__ float  g_sumcur[(size_t)NK * ND];
__device__ float  g_n;

// ---------------- helpers --------------------------------------------------------
__device__ __forceinline__ uint32_t smem_u32(const void* p) {
    uint32_t a;
    asm("{ .reg .u64 t; cvta.to.shared.u64 t, %1; cvt.u32.u64 %0, t; }" : "=r"(a) : "l"(p));
    return a;
}
__device__ __forceinline__ float tf32r(float x) {
    float r;
    asm("cvt.rna.tf32.f32 %0, %1;" : "=f"(r) : "f"(x));
    return r;
}
__device__ __forceinline__ uint32_t swz(uint32_t off) { return off ^ ((off >> 3) & 0x70); }

__device__ __forceinline__ void ldm_x4(uint32_t& r0, uint32_t& r1, uint32_t& r2, uint32_t& r3, uint32_t a) {
    asm volatile("ldmatrix.sync.aligned.m8n8.x4.shared.b16 {%0,%1,%2,%3}, [%4];"
                 : "=r"(r0), "=r"(r1), "=r"(r2), "=r"(r3) : "r"(a));
}
__device__ __forceinline__ void ldm_x2(uint32_t& r0, uint32_t& r1, uint32_t a) {
    asm volatile("ldmatrix.sync.aligned.m8n8.x2.shared.b16 {%0,%1}, [%2];"
                 : "=r"(r0), "=r"(r1) : "r"(a));
}
__device__ __forceinline__ void mma8(float* c, const uint32_t* a, const uint32_t* b) {
    asm volatile("mma.sync.aligned.m16n8k8.row.col.f32.tf32.tf32.f32 "
        "{%0,%1,%2,%3}, {%4,%5,%6,%7}, {%8,%9}, {%0,%1,%2,%3};"
        : "+f"(c[0]), "+f"(c[1]), "+f"(c[2]), "+f"(c[3])
        : "r"(a[0]), "r"(a[1]), "r"(a[2]), "r"(a[3]), "r"(b[0]), "r"(b[1]));
}
#define CP_ASYNC16(dst, src) asm volatile("cp.async.cg.shared.global [%0], [%1], 16;" :: "r"(dst), "l"(src))
#define CP_COMMIT()  asm volatile("cp.async.commit_group;" ::: "memory")
#define CP_WAIT0()   asm volatile("cp.async.wait_group 0;" ::: "memory")

// smem stage: A_hi[128 rows x 128B] | A_lo | B_hi[136 rows x 32B] | B_lo
#define O_ALO 16384
#define O_BHI 32768
#define O_BLO (32768 + 4608)
#define STAGE 41984                          // 41 KB, 1024-aligned
#define O_STAT (2 * STAGE)
#define SMEM_MMA (O_STAT + 2048)

// ---------------- weight split + permute prep (per layer) -----------------------
// in: w[oc][ch][kk]  ->  out[oc][ch>>3][kk][ch&7], tf32 hi/lo split
__global__ void wsplit_kernel(const float* __restrict__ w)
{
    int i = blockIdx.x * 256 + threadIdx.x;      // 65536 = (oc, ch)
    int oc = i >> 8, ch = i & 255;
    float4 v = *(const float4*)&w[(size_t)oc * 1024 + ch * 4];
    size_t base = (size_t)oc * 1024 + (ch >> 3) * 32 + (ch & 7);
#pragma unroll
    for (int kk = 0; kk < 4; kk++) {
        float x = (&v.x)[kk];
        float hi = tf32r(x);
        g_whi[base + kk * 8] = hi;
        g_wlo[base + kk * 8] = tf32r(x - hi);
    }
}

// ============ conv D->D: pipelined mma.sync tf32 3x-split, tap-shifted B ========
// C[128 oc][128 tok]; K = 32 chunks of (8 ch x 4 taps). Single barrier per chunk;
// per k-step all fragments are loaded first, then pass-grouped MMAs (16+16+16).
__global__ __launch_bounds__(256, 1) void convmma_kernel(
    const float* __restrict__ in, const float* __restrict__ bias,
    float* __restrict__ out, int Lin, int Lout, int pad, int tstride, int do_stats)
{
    extern __shared__ __align__(1024) char smem[];
    const int tid = threadIdx.x;
    const int wid = tid >> 5, lane = tid & 31;
    const int b = blockIdx.z, oc0 = blockIdx.y * 128, t0 = blockIdx.x * 128;
    const int ocw = (wid & 1) * 64;
    const int tokw = (wid >> 1) * 32;

    const uint32_t sb = smem_u32(smem);
    const float* xb = in + (size_t)b * TS_INT * ND;

    // A fragment bases (within stage, SW128 rows of 128B)
    uint32_t abase[4];
    {
        int ar = ocw + (lane & 7) + ((lane >> 3) & 1) * 8;
        int aq = (lane >> 4) & 1;
#pragma unroll
        for (int mt = 0; mt < 4; mt++) {
            int r = ar + mt * 16;
            abase[mt] = (uint32_t)(r * 128 + ((aq * 16) ^ ((r & 7) << 4)));
        }
    }
    // B per-lane ldmatrix row base (32B swizzled rows)
    const int lb = lane & 15;
    const int rb0 = tokw + (lb & 7);
    const uint32_t sg = (uint32_t)(((lb >> 3) & 1) << 4);

    float C[4][4][4];
#pragma unroll
    for (int mt = 0; mt < 4; mt++)
#pragma unroll
        for (int nt = 0; nt < 4; nt++)
#pragma unroll
            for (int q = 0; q < 4; q++) C[mt][nt][q] = 0.f;

    // ---- B prefetch state: thread -> (token j = tid>>1, seg h = tid&1) ---------
    const int jj = tid >> 1, hh = tid & 1;
    const int jx = 128 + (tid >> 1);             // extra rows 128..130 for tid<6
    float4 bpre0, bpre1, spre, hpre;

    // ---- prologue: stage 0 -----------------------------------------------------
    {
        const float* whp = g_whi + (size_t)oc0 * 1024;
        const float* wlp = g_wlo + (size_t)oc0 * 1024;
#pragma unroll
        for (int it = 0; it < 8; it++) {
            int idx = tid + it * 256, r = idx >> 3, ql = idx & 7, rr = r & 127;
            const float* src = ((r < 128) ? whp : wlp) + (size_t)rr * 1024 + ql * 4;
            uint32_t dst = sb + ((r < 128) ? 0u : (uint32_t)O_ALO) + swz((uint32_t)(rr * 128 + ql * 16));
            CP_ASYNC16(dst, src);
        }
        CP_COMMIT();
        int ti = t0 - pad + jj;
        bpre0 = ((unsigned)ti < (unsigned)Lin) ? *(const float4*)&xb[(size_t)ti * ND + hh * 4]
                                               : make_float4(0.f, 0.f, 0.f, 0.f);
        if (tid < 6) {
            int t2 = t0 - pad + jx;
            bpre1 = ((unsigned)t2 < (unsigned)Lin) ? *(const float4*)&xb[(size_t)t2 * ND + hh * 4]
                                                   : make_float4(0.f, 0.f, 0.f, 0.f);
        }
        spre = *(const float4*)&g_scale[hh * 4];
        hpre = *(const float4*)&g_shift[hh * 4];
    }

    for (int cc = 0; cc < 32; cc++) {
        const uint32_t su = sb + (cc & 1) * STAGE;
        char* st = smem + (cc & 1) * STAGE;

        CP_WAIT0();
        // ---- STS B from prefetch regs (BN+ReLU+split at store time) -----------
        {
            int ti = t0 - pad + jj;
            bool ok = (unsigned)ti < (unsigned)Lin;
            float4 hi4, lo4;
#pragma unroll
            for (int q = 0; q < 4; q++) {
                float v = ok ? fmaxf(fmaf((&bpre0.x)[q], (&spre.x)[q], (&hpre.x)[q]), 0.f) : 0.f;
                float h = tf32r(v);
                (&hi4.x)[q] = h; (&lo4.x)[q] = tf32r(v - h);
            }
            uint32_t byte = (uint32_t)(jj * 32 + hh * 16) ^ ((uint32_t)(jj & 4) << 2);
            *(float4*)(st + O_BHI + byte) = hi4;
            *(float4*)(st + O_BLO + byte) = lo4;
            if (tid < 6) {
                int t2 = t0 - pad + jx;
                bool ok2 = (unsigned)t2 < (unsigned)Lin;
                float4 hi2, lo2;
#pragma unroll
                for (int q = 0; q < 4; q++) {
                    float v = ok2 ? fmaxf(fmaf((&bpre1.x)[q], (&spre.x)[q], (&hpre.x)[q]), 0.f) : 0.f;
                    float h = tf32r(v);
                    (&hi2.x)[q] = h; (&lo2.x)[q] = tf32r(v - h);
                }
                uint32_t byte2 = (uint32_t)(jx * 32 + hh * 16) ^ ((uint32_t)(jx & 4) << 2);
                *(float4*)(st + O_BHI + byte2) = hi2;
                *(float4*)(st + O_BLO + byte2) = lo2;
            }
        }
        __syncthreads();      // single barrier per chunk (tail barrier proven redundant)

        // ---- prefetch chunk cc+1 (A via cp.async, B via regs) ------------------
        if (cc + 1 < 32) {
            const float* whp = g_whi + (size_t)oc0 * 1024 + (cc + 1) * 32;
            const float* wlp = g_wlo + (size_t)oc0 * 1024 + (cc + 1) * 32;
            uint32_t sd = sb + ((cc + 1) & 1) * STAGE;
#pragma unroll
            for (int it = 0; it < 8; it++) {
                int idx = tid + it * 256, r = idx >> 3, ql = idx & 7, rr = r & 127;
                const float* src = ((r < 128) ? whp : wlp) + (size_t)rr * 1024 + ql * 4;
                uint32_t dst = sd + ((r < 128) ? 0u : (uint32_t)O_ALO) + swz((uint32_t)(rr * 128 + ql * 16));
                CP_ASYNC16(dst, src);
            }
            CP_COMMIT();
            const int ch0 = (cc + 1) * 8;
            int ti = t0 - pad + jj;
            bpre0 = ((unsigned)ti < (unsigned)Lin) ? *(const float4*)&xb[(size_t)ti * ND + ch0 + hh * 4]
                                                   : make_float4(0.f, 0.f, 0.f, 0.f);
            if (tid < 6) {
                int t2 = t0 - pad + jx;
                bpre1 = ((unsigned)t2 < (unsigned)Lin) ? *(const float4*)&xb[(size_t)t2 * ND + ch0 + hh * 4]
                                                       : make_float4(0.f, 0.f, 0.f, 0.f);
            }
            spre = *(const float4*)&g_scale[ch0 + hh * 4];
            hpre = *(const float4*)&g_shift[ch0 + hh * 4];
        }

        // ---- mma on chunk cc: load ALL fragments per k-step, pass-grouped MMAs -
#pragma unroll
        for (int ks = 0; ks < 4; ks++) {
            uint32_t bh[4][2], bl[4][2], ah[4][4], al[4][4];
#pragma unroll
            for (int nt = 0; nt < 4; nt++) {
                int r = rb0 + nt * 8 + ks;
                uint32_t byte = ((uint32_t)(r * 32) + sg) ^ ((uint32_t)(r & 4) << 2);
                uint32_t ad = su + O_BHI + byte;
                ldm_x2(bh[nt][0], bh[nt][1], ad);
                ldm_x2(bl[nt][0], bl[nt][1], ad + (O_BLO - O_BHI));
            }
#pragma unroll
            for (int mt = 0; mt < 4; mt++) {
                uint32_t ad = su + (abase[mt] ^ (uint32_t)(ks << 5));
                ldm_x4(ah[mt][0], ah[mt][1], ah[mt][2], ah[mt][3], ad);
                ldm_x4(al[mt][0], al[mt][1], al[mt][2], al[mt][3], ad + O_ALO);
            }
            // pass 1: hi*hi — 16 independent accumulators
#pragma unroll
            for (int mt = 0; mt < 4; mt++)
#pragma unroll
                for (int nt = 0; nt < 4; nt++) mma8(C[mt][nt], ah[mt], bh[nt]);
            // pass 2: hi*lo
#pragma unroll
            for (int mt = 0; mt < 4; mt++)
#pragma unroll
                for (int nt = 0; nt < 4; nt++) mma8(C[mt][nt], ah[mt], bl[nt]);
            // pass 3: lo*hi
#pragma unroll
            for (int mt = 0; mt < 4; mt++)
#pragma unroll
                for (int nt = 0; nt < 4; nt++) mma8(C[mt][nt], al[mt], bh[nt]);
        }
    }
    __syncthreads();

    // ---- epilogue: bias + BN stats + smem transpose + coalesced store ----------
    double* ssumS = (double*)(smem + O_STAT);
    double* ssqS  = (double*)(smem + O_STAT + 1024);
    if (tid < 128) { ssumS[tid] = 0.0; ssqS[tid] = 0.0; }
    float* eb = (float*)smem;                 // [128 tok][132 oc]
    __syncthreads();

#pragma unroll
    for (int mt = 0; mt < 4; mt++) {
#pragma unroll
        for (int h = 0; h < 2; h++) {
            int ocl = ocw + mt * 16 + (lane >> 2) + h * 8;
            float bv = bias[oc0 + ocl];
            double s = 0.0, q = 0.0;
#pragma unroll
            for (int nt = 0; nt < 4; nt++) {
#pragma unroll
                for (int p = 0; p < 2; p++) {
                    int n = tokw + nt * 8 + (lane & 3) * 2 + p;
                    float v = C[mt][nt][h * 2 + p] + bv;
                    eb[n * 132 + ocl] = v;
                    if (do_stats && (t0 + n < Lout)) { double d = (double)v; s += d; q += d * d; }
                }
            }
            if (do_stats) { atomicAdd(&ssumS[ocl], s); atomicAdd(&ssqS[ocl], q); }
        }
    }
    __syncthreads();

    for (int idx = tid; idx < 4096; idx += 256) {
        int r = idx >> 5, ql = idx & 31;
        if (t0 + r < Lout)
            *(float4*)&out[((size_t)b * tstride + t0 + r) * ND + oc0 + ql * 4] =
                *(float4*)&eb[r * 132 + ql * 4];
    }
    if (do_stats && tid < 128) {
        atomicAdd(&g_sum[oc0 + tid], ssumS[tid]);
        atomicAdd(&g_sumsq[oc0 + tid], ssqS[tid]);
    }
}

// ---------------- layer 1: conv 12 -> 256, k=4, pad=2 (scalar; tiny K) ----------
__global__ __launch_bounds__(256) void conv1_kernel(
    const float* __restrict__ x, const float* __restrict__ w,
    const float* __restrict__ bias, float* __restrict__ out)
{
    __shared__ float in_s[12][68];
    __shared__ float w_s[64][49];
    __shared__ float o_s[64][65];
    __shared__ double ssum[64], ssq[64];

    const int tid = threadIdx.x;
    const int b = blockIdx.z, oc0 = blockIdx.y * 64, t0 = blockIdx.x * 64;
    const int ocl = tid & 63, tg = tid >> 6, tbase = tg * 16;
    const int Lout = 4097;

    for (int idx = tid; idx < 12 * 67; idx += 256) {
        int j = idx / 12, c = idx - j * 12;
        int ip = t0 - 2 + j;
        in_s[c][j] = ((unsigned)ip < 4096u) ? x[((size_t)b * NT + ip) * 12 + c] : 0.f;
    }
    for (int idx = tid; idx < 64 * 48; idx += 256) {
        int oc = idx / 48, r = idx - oc * 48;
        w_s[oc][r] = w[(size_t)(oc0 + oc) * 48 + r];
    }
    __syncthreads();

    float acc[16];
#pragma unroll
    for (int u = 0; u < 16; u++) acc[u] = 0.f;
#pragma unroll
    for (int c = 0; c < 12; c++) {
        float v[19];
#pragma unroll
        for (int u = 0; u < 19; u++) v[u] = in_s[c][tbase + u];
        float w0 = w_s[ocl][c * 4 + 0], w1 = w_s[ocl][c * 4 + 1];
        float w2 = w_s[ocl][c * 4 + 2], w3 = w_s[ocl][c * 4 + 3];
#pragma unroll
        for (int u = 0; u < 16; u++)
            acc[u] = fmaf(w3, v[u + 3], fmaf(w2, v[u + 2], fmaf(w1, v[u + 1], fmaf(w0, v[u], acc[u]))));
    }
    const float bv = bias[oc0 + ocl];
#pragma unroll
    for (int u = 0; u < 16; u++) acc[u] += bv;

    {
        double s = 0.0, q = 0.0;
#pragma unroll
        for (int u = 0; u < 16; u++)
            if (t0 + tbase + u < Lout) { double a = (double)acc[u]; s += a; q += a * a; }
        __syncthreads();
        if (tid < 64) { ssum[tid] = 0.0; ssq[tid] = 0.0; }
        __syncthreads();
        atomicAdd(&ssum[ocl], s);
        atomicAdd(&ssq[ocl], q);
        __syncthreads();
        if (tid < 64) {
            atomicAdd(&g_sum[oc0 + tid], ssum[tid]);
            atomicAdd(&g_sumsq[oc0 + tid], ssq[tid]);
        }
    }

    __syncthreads();
#pragma unroll
    for (int u = 0; u < 16; u++) o_s[ocl][tbase + u] = acc[u];
    __syncthreads();
    float* ob = out + ((size_t)b * TS_INT + t0) * ND + oc0;
    for (int idx = tid; idx < 4096; idx += 256) {
        int t = idx >> 6, oc = idx & 63;
        if (t0 + t < Lout) ob[(size_t)t * ND + oc] = o_s[oc][t];
    }
}

// ---------------- BN stats -> scale/shift for next layer; resets stats ----------
__global__ void scaleshift_kernel(const float* __restrict__ g, const float* __restrict__ be, double N)
{
    int c = threadIdx.x;
    double m = g_sum[c] / N;
    double var = g_sumsq[c] / N - m * m;
    double r = 1.0 / sqrt(var + 1e-5);
    double sc = (double)g[c] * r;
    g_scale[c] = (float)sc;
    g_shift[c] = (float)((double)be[c] - m * sc);
    g_sum[c] = 0.0;
    g_sumsq[c] = 0.0;
}

// ---------------- ||codebook_k||^2 ----------------------------------------------
__global__ void cnorm_kernel(const float* __restrict__ cb)
{
    int gw = (blockIdx.x * 256 + threadIdx.x) >> 5;
    int lane = threadIdx.x & 31;
    float s = 0.f;
    const float* row = cb + (size_t)gw * ND;
    for (int d = lane; d < ND; d += 32) { float v = row[d]; s = fmaf(v, v, s); }
#pragma unroll
    for (int off = 16; off; off >>= 1) s += __shfl_xor_sync(0xffffffffu, s, off);
    if (lane == 0) g_cnorm[gw] = s;
}

// ---------------- VQ: argmin + z_q write + counts + segment sums ----------------
__global__ __launch_bounds__(256) void vq_kernel(
    const float* __restrict__ ze, const float* __restrict__ cb, float* __restrict__ zq)
{
    __shared__ float z_s[64][17];
    __shared__ float c_s[128][17];
    __shared__ int sbest[64];

    const int tid = threadIdx.x;
    const int tok0 = blockIdx.x * 64;
    const int tokg = tid >> 4;
    const int codeg = tid & 15;

    float bval[4];
    int bidx[4];
#pragma unroll
    for (int i = 0; i < 4; i++) { bval[i] = 1e30f; bidx[i] = 0x7fffffff; }

    for (int ct = 0; ct < NK; ct += 128) {
        float acc[4][8];
#pragma unroll
        for (int i = 0; i < 4; i++)
#pragma unroll
            for (int j = 0; j < 8; j++) acc[i][j] = 0.f;

        for (int d0 = 0; d0 < ND; d0 += 16) {
            __syncthreads();
            for (int idx = tid; idx < 1024; idx += 256) {
                int r = idx >> 4, dj = idx & 15;
                z_s[r][dj] = ze[(size_t)(tok0 + r) * ND + d0 + dj];
            }
            for (int idx = tid; idx < 2048; idx += 256) {
                int r = idx >> 4, dj = idx & 15;
                c_s[r][dj] = cb[(size_t)(ct + r) * ND + d0 + dj];
            }
            __syncthreads();
#pragma unroll
            for (int dj = 0; dj < 16; dj++) {
                float zr[4], cr[8];
#pragma unroll
                for (int i = 0; i < 4; i++) zr[i] = z_s[tokg * 4 + i][dj];
#pragma unroll
                for (int j = 0; j < 8; j++) cr[j] = c_s[codeg + 16 * j][dj];
#pragma unroll
                for (int i = 0; i < 4; i++)
#pragma unroll
                    for (int j = 0; j < 8; j++)
                        acc[i][j] = fmaf(zr[i], cr[j], acc[i][j]);
            }
        }
#pragma unroll
        for (int j = 0; j < 8; j++) {
            int code = ct + codeg + 16 * j;
            float cn = g_cnorm[code];
#pragma unroll
            for (int i = 0; i < 4; i++) {
                float s = fmaf(-2.f, acc[i][j], cn);
                if (s < bval[i] || (s == bval[i] && code < bidx[i])) { bval[i] = s; bidx[i] = code; }
            }
        }
    }
#pragma unroll
    for (int off = 8; off >= 1; off >>= 1) {
#pragma unroll
        for (int i = 0; i < 4; i++) {
            float ov = __shfl_xor_sync(0xffffffffu, bval[i], off);
            int oi = __shfl_xor_sync(0xffffffffu, bidx[i], off);
            if (ov < bval[i] || (ov == bval[i] && oi < bidx[i])) { bval[i] = ov; bidx[i] = oi; }
        }
    }
    if (codeg == 0) {
#pragma unroll
        for (int i = 0; i < 4; i++) sbest[tokg * 4 + i] = bidx[i];
    }
    __syncthreads();
    if (tid < 64) atomicAdd(&g_cnt[sbest[tid]], 1.0f);
    for (int e = tid; e < 64 * ND; e += 256) {
        int r = e >> 8, d = e & 255;
        int code = sbest[r];
        size_t gz = (size_t)(tok0 + r) * ND + d;
        float zev = ze[gz];
        float cbv = cb[(size_t)code * ND + d];
        zq[gz] = zev + (cbv - zev);
        atomicAdd(&g_sumcur[(size_t)code * ND + d], zev);
    }
}

// ---------------- EMA epilogue ---------------------------------------------------
__global__ void ema1_kernel(const float* __restrict__ ecs, float* __restrict__ necs)
{
    __shared__ float red[1024];
    int k = threadIdx.x;
    float ne = ecs[k] * 0.99f + 0.01f * g_cnt[k];
    necs[k] = ne;
    g_cnt[k] = 0.f;
    red[k] = ne;
    __syncthreads();
    for (int off = 512; off; off >>= 1) {
        if (k < off) red[k] += red[k + off];
        __syncthreads();
    }
    if (k == 0) g_n = red[0];
}

__global__ void ema2_kernel(const float* __restrict__ ema_w, const float* __restrict__ necs,
                            float* __restrict__ ncb)
{
    int k = blockIdx.x, d = threadIdx.x;
    float n = g_n;
    float smoothed = (necs[k] + 1e-5f) / (n + 1024.f * 1e-5f) * n;
    size_t idx = (size_t)k * ND + d;
    float nw = ema_w[idx] * 0.99f + 0.01f * g_sumcur[idx];
    ncb[idx] = nw / smoothed;
    g_sumcur[idx] = 0.f;
}

// ---------------- host launcher ---------------------------------------------------
extern "C" void kernel_launch(void* const* d_in, const int* in_sizes, int n_in,
                              void* d_out, int out_size)
{
    const float* X = (const float*)d_in[0];
    const float *W[6], *Bi[6], *G[5], *Be[5];

    bool sig = (in_sizes[3] == 256);
    if (!sig) {
        for (int i = 0; i < 6; i++) { W[i] = (const float*)d_in[1 + 2 * i]; Bi[i] = (const float*)d_in[2 + 2 * i]; }
        for (int i = 0; i < 5; i++) { G[i] = (const float*)d_in[13 + 2 * i]; Be[i] = (const float*)d_in[14 + 2 * i]; }
    } else {
        for (int i = 0; i < 5; i++) {
            W[i]  = (const float*)d_in[1 + 4 * i];
            Bi[i] = (const float*)d_in[2 + 4 * i];
            G[i]  = (const float*)d_in[3 + 4 * i];
            Be[i] = (const float*)d_in[4 + 4 * i];
        }
        W[5] = (const float*)d_in[21];
        Bi[5] = (const float*)d_in[22];
    }
    const float* codebook = (const float*)d_in[23];
    const float* ema_w    = (const float*)d_in[24];
    const float* ecs      = (const float*)d_in[25];

    float* out  = (float*)d_out;
    float* ze   = out;
    float* zq   = out + (size_t)33554432;
    float* ncb  = out + (size_t)67108864;
    float* necs = out + (size_t)67371008;

    float *bufA = nullptr, *bufB = nullptr;
    cudaGetSymbolAddress((void**)&bufA, g_bufA);
    cudaGetSymbolAddress((void**)&bufB, g_bufB);

    cudaFuncSetAttribute(convmma_kernel, cudaFuncAttributeMaxDynamicSharedMemorySize, SMEM_MMA);

    dim3 blk(256);
    conv1_kernel<<<dim3(65, 4, 32), blk>>>(X, W[0], Bi[0], bufA);
    scaleshift_kernel<<<1, 256>>>(G[0], Be[0], (double)(32.0 * 4097.0));
    wsplit_kernel<<<256, 256>>>(W[1]);
    convmma_kernel<<<dim3(32, 2, 32), blk, SMEM_MMA>>>(bufA, Bi[1], bufB, 4097, 4096, 1, TS_INT, 1);
    scaleshift_kernel<<<1, 256>>>(G[1], Be[1], (double)(32.0 * 4096.0));
    wsplit_kernel<<<256, 256>>>(W[2]);
    convmma_kernel<<<dim3(33, 2, 32), blk, SMEM_MMA>>>(bufB, Bi[2], bufA, 4096, 4097, 2, TS_INT, 1);
    scaleshift_kernel<<<1, 256>>>(G[2], Be[2], (double)(32.0 * 4097.0));
    wsplit_kernel<<<256, 256>>>(W[3]);
    convmma_kernel<<<dim3(32, 2, 32), blk, SMEM_MMA>>>(bufA, Bi[3], bufB, 4097, 4096, 1, TS_INT, 1);
    scaleshift_kernel<<<1, 256>>>(G[3], Be[3], (double)(32.0 * 4096.0));
    wsplit_kernel<<<256, 256>>>(W[4]);
    convmma_kernel<<<dim3(33, 2, 32), blk, SMEM_MMA>>>(bufB, Bi[4], bufA, 4096, 4097, 2, TS_INT, 1);
    scaleshift_kernel<<<1, 256>>>(G[4], Be[4], (double)(32.0 * 4097.0));
    wsplit_kernel<<<256, 256>>>(W[5]);
    convmma_kernel<<<dim3(32, 2, 32), blk, SMEM_MMA>>>(bufA, Bi[5], ze, 4097, 4096, 1, 4096, 0);

    cnorm_kernel<<<128, 256>>>(codebook);
    vq_kernel<<<2048, 256>>>(ze, codebook, zq);
    ema1_kernel<<<1, 1024>>>(ecs, necs);
    ema2_kernel<<<1024, 256>>>(ema_w, necs, ncb);
}

// round 7
// speedup vs baseline: 1.5583x; 1.0239x over previous
#include <cuda_runtime.h>
#include <cstdint>

#define NB 32
#define NT 4096
#define ND 256
#define NK 1024
#define TS_INT 4104        // token stride of intermediate activation buffers

// ---------------- scratch (static device globals; no allocation) ----------------
__device__ float  g_bufA[(size_t)NB * TS_INT * ND];
__device__ float  g_bufB[(size_t)NB * TS_INT * ND];
__device__ float  g_whi[(size_t)ND * 1024];     // permuted: [oc][chunk][kk][ch&7]
__device__ float  g_wlo[(size_t)ND * 1024];
__device__ double g_sum[ND];
__device__ double g_sumsq[ND];
__device__ float  g_scale[ND];
__device__ float  g_shift[ND];
__device__ float  g_cnorm[NK];
__device__ float  g_cnt[NK];
__device__ float  g_sumcur[(size_t)NK * ND];
__device__ float  g_n;

// ---------------- helpers --------------------------------------------------------
__device__ __forceinline__ uint32_t smem_u32(const void* p) {
    uint32_t a;
    asm("{ .reg .u64 t; cvta.to.shared.u64 t, %1; cvt.u32.u64 %0, t; }" : "=r"(a) : "l"(p));
    return a;
}
__device__ __forceinline__ float tf32r(float x) {
    float r;
    asm("cvt.rna.tf32.f32 %0, %1;" : "=f"(r) : "f"(x));
    return r;
}
__device__ __forceinline__ uint32_t swz(uint32_t off) { return off ^ ((off >> 3) & 0x70); }

__device__ __forceinline__ void ldm_x4(uint32_t& r0, uint32_t& r1, uint32_t& r2, uint32_t& r3, uint32_t a) {
    asm volatile("ldmatrix.sync.aligned.m8n8.x4.shared.b16 {%0,%1,%2,%3}, [%4];"
                 : "=r"(r0), "=r"(r1), "=r"(r2), "=r"(r3) : "r"(a));
}
__device__ __forceinline__ void mma8(float* c, const uint32_t* a, const uint32_t* b) {
    asm volatile("mma.sync.aligned.m16n8k8.row.col.f32.tf32.tf32.f32 "
        "{%0,%1,%2,%3}, {%4,%5,%6,%7}, {%8,%9}, {%0,%1,%2,%3};"
        : "+f"(c[0]), "+f"(c[1]), "+f"(c[2]), "+f"(c[3])
        : "r"(a[0]), "r"(a[1]), "r"(a[2]), "r"(a[3]), "r"(b[0]), "r"(b[1]));
}
#define CP_ASYNC16(dst, src) asm volatile("cp.async.cg.shared.global [%0], [%1], 16;" :: "r"(dst), "l"(src))
#define CP_COMMIT()  asm volatile("cp.async.commit_group;" ::: "memory")
#define CP_WAIT0()   asm volatile("cp.async.wait_group 0;" ::: "memory")

// smem stage: A_hi[128 rows x 128B] | A_lo | B_hi[136 rows x 32B] | B_lo
#define O_ALO 16384
#define O_BHI 32768
#define O_BLO (32768 + 4608)
#define STAGE 41984                          // 41 KB, 1024-aligned
#define O_STAT (2 * STAGE)
#define SMEM_MMA (O_STAT + 2048)

// ---------------- weight split + permute prep (per layer) -----------------------
// in: w[oc][ch][kk]  ->  out[oc][ch>>3][kk][ch&7], tf32 hi/lo split
__global__ void wsplit_kernel(const float* __restrict__ w)
{
    int i = blockIdx.x * 256 + threadIdx.x;      // 65536 = (oc, ch)
    int oc = i >> 8, ch = i & 255;
    float4 v = *(const float4*)&w[(size_t)oc * 1024 + ch * 4];
    size_t base = (size_t)oc * 1024 + (ch >> 3) * 32 + (ch & 7);
#pragma unroll
    for (int kk = 0; kk < 4; kk++) {
        float x = (&v.x)[kk];
        float hi = tf32r(x);
        g_whi[base + kk * 8] = hi;
        g_wlo[base + kk * 8] = tf32r(x - hi);
    }
}

// ============ conv D->D: pipelined mma.sync tf32 3x-split, tap-shifted B ========
// C[128 oc][128 tok]; K = 32 chunks of (8 ch x 4 taps). B fragments loaded as
// paired ldmatrix.x4 (2 n-tiles per instr); A_lo loads deferred past hi passes.
__global__ __launch_bounds__(256, 1) void convmma_kernel(
    const float* __restrict__ in, const float* __restrict__ bias,
    float* __restrict__ out, int Lin, int Lout, int pad, int tstride, int do_stats)
{
    extern __shared__ __align__(1024) char smem[];
    const int tid = threadIdx.x;
    const int wid = tid >> 5, lane = tid & 31;
    const int b = blockIdx.z, oc0 = blockIdx.y * 128, t0 = blockIdx.x * 128;
    const int ocw = (wid & 1) * 64;
    const int tokw = (wid >> 1) * 32;

    const uint32_t sb = smem_u32(smem);
    const float* xb = in + (size_t)b * TS_INT * ND;

    // A fragment bases (within stage, SW128 rows of 128B)
    uint32_t abase[4];
    {
        int ar = ocw + (lane & 7) + ((lane >> 3) & 1) * 8;
        int aq = (lane >> 4) & 1;
#pragma unroll
        for (int mt = 0; mt < 4; mt++) {
            int r = ar + mt * 16;
            abase[mt] = (uint32_t)(r * 128 + ((aq * 16) ^ ((r & 7) << 4)));
        }
    }
    // B paired-x4 per-lane row base: group g=lane>>3 -> (col16 = g&1, +8 rows = g>>1)
    const int brow0 = tokw + (lane & 7) + (((lane >> 4) & 1) << 3);
    const uint32_t bcol = (uint32_t)(((lane >> 3) & 1) << 4);

    float C[4][4][4];
#pragma unroll
    for (int mt = 0; mt < 4; mt++)
#pragma unroll
        for (int nt = 0; nt < 4; nt++)
#pragma unroll
            for (int q = 0; q < 4; q++) C[mt][nt][q] = 0.f;

    // ---- B prefetch state: thread -> (token j = tid>>1, seg h = tid&1) ---------
    const int jj = tid >> 1, hh = tid & 1;
    const int jx = 128 + (tid >> 1);             // extra rows 128..130 for tid<6
    float4 bpre0, bpre1, spre, hpre;

    // ---- prologue: stage 0 -----------------------------------------------------
    {
        const float* whp = g_whi + (size_t)oc0 * 1024;
        const float* wlp = g_wlo + (size_t)oc0 * 1024;
#pragma unroll
        for (int it = 0; it < 8; it++) {
            int idx = tid + it * 256, r = idx >> 3, ql = idx & 7, rr = r & 127;
            const float* src = ((r < 128) ? whp : wlp) + (size_t)rr * 1024 + ql * 4;
            uint32_t dst = sb + ((r < 128) ? 0u : (uint32_t)O_ALO) + swz((uint32_t)(rr * 128 + ql * 16));
            CP_ASYNC16(dst, src);
        }
        CP_COMMIT();
        int ti = t0 - pad + jj;
        bpre0 = ((unsigned)ti < (unsigned)Lin) ? *(const float4*)&xb[(size_t)ti * ND + hh * 4]
                                               : make_float4(0.f, 0.f, 0.f, 0.f);
        if (tid < 6) {
            int t2 = t0 - pad + jx;
            bpre1 = ((unsigned)t2 < (unsigned)Lin) ? *(const float4*)&xb[(size_t)t2 * ND + hh * 4]
                                                   : make_float4(0.f, 0.f, 0.f, 0.f);
        }
        spre = *(const float4*)&g_scale[hh * 4];
        hpre = *(const float4*)&g_shift[hh * 4];
    }

    for (int cc = 0; cc < 32; cc++) {
        const uint32_t su = sb + (cc & 1) * STAGE;
        char* st = smem + (cc & 1) * STAGE;

        CP_WAIT0();
        // ---- STS B from prefetch regs (BN+ReLU+split at store time) -----------
        {
            int ti = t0 - pad + jj;
            bool ok = (unsigned)ti < (unsigned)Lin;
            float4 hi4, lo4;
#pragma unroll
            for (int q = 0; q < 4; q++) {
                float v = ok ? fmaxf(fmaf((&bpre0.x)[q], (&spre.x)[q], (&hpre.x)[q]), 0.f) : 0.f;
                float h = tf32r(v);
                (&hi4.x)[q] = h; (&lo4.x)[q] = tf32r(v - h);
            }
            uint32_t byte = (uint32_t)(jj * 32 + hh * 16) ^ ((uint32_t)(jj & 4) << 2);
            *(float4*)(st + O_BHI + byte) = hi4;
            *(float4*)(st + O_BLO + byte) = lo4;
            if (tid < 6) {
                int t2 = t0 - pad + jx;
                bool ok2 = (unsigned)t2 < (unsigned)Lin;
                float4 hi2, lo2;
#pragma unroll
                for (int q = 0; q < 4; q++) {
                    float v = ok2 ? fmaxf(fmaf((&bpre1.x)[q], (&spre.x)[q], (&hpre.x)[q]), 0.f) : 0.f;
                    float h = tf32r(v);
                    (&hi2.x)[q] = h; (&lo2.x)[q] = tf32r(v - h);
                }
                uint32_t byte2 = (uint32_t)(jx * 32 + hh * 16) ^ ((uint32_t)(jx & 4) << 2);
                *(float4*)(st + O_BHI + byte2) = hi2;
                *(float4*)(st + O_BLO + byte2) = lo2;
            }
        }
        __syncthreads();      // single barrier per chunk

        // ---- prefetch chunk cc+1 (A via cp.async, B via regs) ------------------
        if (cc + 1 < 32) {
            const float* whp = g_whi + (size_t)oc0 * 1024 + (cc + 1) * 32;
            const float* wlp = g_wlo + (size_t)oc0 * 1024 + (cc + 1) * 32;
            uint32_t sd = sb + ((cc + 1) & 1) * STAGE;
#pragma unroll
            for (int it = 0; it < 8; it++) {
                int idx = tid + it * 256, r = idx >> 3, ql = idx & 7, rr = r & 127;
                const float* src = ((r < 128) ? whp : wlp) + (size_t)rr * 1024 + ql * 4;
                uint32_t dst = sd + ((r < 128) ? 0u : (uint32_t)O_ALO) + swz((uint32_t)(rr * 128 + ql * 16));
                CP_ASYNC16(dst, src);
            }
            CP_COMMIT();
            const int ch0 = (cc + 1) * 8;
            int ti = t0 - pad + jj;
            bpre0 = ((unsigned)ti < (unsigned)Lin) ? *(const float4*)&xb[(size_t)ti * ND + ch0 + hh * 4]
                                                   : make_float4(0.f, 0.f, 0.f, 0.f);
            if (tid < 6) {
                int t2 = t0 - pad + jx;
                bpre1 = ((unsigned)t2 < (unsigned)Lin) ? *(const float4*)&xb[(size_t)t2 * ND + ch0 + hh * 4]
                                                       : make_float4(0.f, 0.f, 0.f, 0.f);
            }
            spre = *(const float4*)&g_scale[ch0 + hh * 4];
            hpre = *(const float4*)&g_shift[ch0 + hh * 4];
        }

        // ---- mma on chunk cc: paired-x4 B loads, deferred A_lo -----------------
#pragma unroll
        for (int ks = 0; ks < 4; ks++) {
            uint32_t bh[4][2], bl[4][2], ah[4][4], al[4][4];
            // B: 2 paired x4 loads cover 4 n-tiles (hi), 2 more for lo
#pragma unroll
            for (int p = 0; p < 2; p++) {
                int r = brow0 + p * 16 + ks;
                uint32_t byte = ((uint32_t)(r * 32) + bcol) ^ ((uint32_t)(r & 4) << 2);
                uint32_t ad = su + O_BHI + byte;
                ldm_x4(bh[2 * p][0], bh[2 * p][1], bh[2 * p + 1][0], bh[2 * p + 1][1], ad);
                ldm_x4(bl[2 * p][0], bl[2 * p][1], bl[2 * p + 1][0], bl[2 * p + 1][1],
                       ad + (O_BLO - O_BHI));
            }
            // A hi
#pragma unroll
            for (int mt = 0; mt < 4; mt++) {
                uint32_t ad = su + (abase[mt] ^ (uint32_t)(ks << 5));
                ldm_x4(ah[mt][0], ah[mt][1], ah[mt][2], ah[mt][3], ad);
            }
            // pass 1: hi*hi
#pragma unroll
            for (int mt = 0; mt < 4; mt++)
#pragma unroll
                for (int nt = 0; nt < 4; nt++) mma8(C[mt][nt], ah[mt], bh[nt]);
            // pass 2: hi*lo
#pragma unroll
            for (int mt = 0; mt < 4; mt++)
#pragma unroll
                for (int nt = 0; nt < 4; nt++) mma8(C[mt][nt], ah[mt], bl[nt]);
            // A lo (deferred — lowers peak register pressure)
#pragma unroll
            for (int mt = 0; mt < 4; mt++) {
                uint32_t ad = su + (abase[mt] ^ (uint32_t)(ks << 5)) + O_ALO;
                ldm_x4(al[mt][0], al[mt][1], al[mt][2], al[mt][3], ad);
            }
            // pass 3: lo*hi
#pragma unroll
            for (int mt = 0; mt < 4; mt++)
#pragma unroll
                for (int nt = 0; nt < 4; nt++) mma8(C[mt][nt], al[mt], bh[nt]);
        }
    }
    __syncthreads();

    // ---- epilogue: bias + BN stats + smem transpose + coalesced store ----------
    double* ssumS = (double*)(smem + O_STAT);
    double* ssqS  = (double*)(smem + O_STAT + 1024);
    if (tid < 128) { ssumS[tid] = 0.0; ssqS[tid] = 0.0; }
    float* eb = (float*)smem;                 // [128 tok][132 oc]
    __syncthreads();

#pragma unroll
    for (int mt = 0; mt < 4; mt++) {
#pragma unroll
        for (int h = 0; h < 2; h++) {
            int ocl = ocw + mt * 16 + (lane >> 2) + h * 8;
            float bv = bias[oc0 + ocl];
            double s = 0.0, q = 0.0;
#pragma unroll
            for (int nt = 0; nt < 4; nt++) {
#pragma unroll
                for (int p = 0; p < 2; p++) {
                    int n = tokw + nt * 8 + (lane & 3) * 2 + p;
                    float v = C[mt][nt][h * 2 + p] + bv;
                    eb[n * 132 + ocl] = v;
                    if (do_stats && (t0 + n < Lout)) { double d = (double)v; s += d; q += d * d; }
                }
            }
            if (do_stats) { atomicAdd(&ssumS[ocl], s); atomicAdd(&ssqS[ocl], q); }
        }
    }
    __syncthreads();

    for (int idx = tid; idx < 4096; idx += 256) {
        int r = idx >> 5, ql = idx & 31;
        if (t0 + r < Lout)
            *(float4*)&out[((size_t)b * tstride + t0 + r) * ND + oc0 + ql * 4] =
                *(float4*)&eb[r * 132 + ql * 4];
    }
    if (do_stats && tid < 128) {
        atomicAdd(&g_sum[oc0 + tid], ssumS[tid]);
        atomicAdd(&g_sumsq[oc0 + tid], ssqS[tid]);
    }
}

// ---------------- layer 1: conv 12 -> 256, k=4, pad=2 (scalar; tiny K) ----------
__global__ __launch_bounds__(256) void conv1_kernel(
    const float* __restrict__ x, const float* __restrict__ w,
    const float* __restrict__ bias, float* __restrict__ out)
{
    __shared__ float in_s[12][68];
    __shared__ float w_s[64][49];
    __shared__ float o_s[64][65];
    __shared__ double ssum[64], ssq[64];

    const int tid = threadIdx.x;
    const int b = blockIdx.z, oc0 = blockIdx.y * 64, t0 = blockIdx.x * 64;
    const int ocl = tid & 63, tg = tid >> 6, tbase = tg * 16;
    const int Lout = 4097;

    for (int idx = tid; idx < 12 * 67; idx += 256) {
        int j = idx / 12, c = idx - j * 12;
        int ip = t0 - 2 + j;
        in_s[c][j] = ((unsigned)ip < 4096u) ? x[((size_t)b * NT + ip) * 12 + c] : 0.f;
    }
    for (int idx = tid; idx < 64 * 48; idx += 256) {
        int oc = idx / 48, r = idx - oc * 48;
        w_s[oc][r] = w[(size_t)(oc0 + oc) * 48 + r];
    }
    __syncthreads();

    float acc[16];
#pragma unroll
    for (int u = 0; u < 16; u++) acc[u] = 0.f;
#pragma unroll
    for (int c = 0; c < 12; c++) {
        float v[19];
#pragma unroll
        for (int u = 0; u < 19; u++) v[u] = in_s[c][tbase + u];
        float w0 = w_s[ocl][c * 4 + 0], w1 = w_s[ocl][c * 4 + 1];
        float w2 = w_s[ocl][c * 4 + 2], w3 = w_s[ocl][c * 4 + 3];
#pragma unroll
        for (int u = 0; u < 16; u++)
            acc[u] = fmaf(w3, v[u + 3], fmaf(w2, v[u + 2], fmaf(w1, v[u + 1], fmaf(w0, v[u], acc[u]))));
    }
    const float bv = bias[oc0 + ocl];
#pragma unroll
    for (int u = 0; u < 16; u++) acc[u] += bv;

    {
        double s = 0.0, q = 0.0;
#pragma unroll
        for (int u = 0; u < 16; u++)
            if (t0 + tbase + u < Lout) { double a = (double)acc[u]; s += a; q += a * a; }
        __syncthreads();
        if (tid < 64) { ssum[tid] = 0.0; ssq[tid] = 0.0; }
        __syncthreads();
        atomicAdd(&ssum[ocl], s);
        atomicAdd(&ssq[ocl], q);
        __syncthreads();
        if (tid < 64) {
            atomicAdd(&g_sum[oc0 + tid], ssum[tid]);
            atomicAdd(&g_sumsq[oc0 + tid], ssq[tid]);
        }
    }

    __syncthreads();
#pragma unroll
    for (int u = 0; u < 16; u++) o_s[ocl][tbase + u] = acc[u];
    __syncthreads();
    float* ob = out + ((size_t)b * TS_INT + t0) * ND + oc0;
    for (int idx = tid; idx < 4096; idx += 256) {
        int t = idx >> 6, oc = idx & 63;
        if (t0 + t < Lout) ob[(size_t)t * ND + oc] = o_s[oc][t];
    }
}

// ---------------- BN stats -> scale/shift for next layer; resets stats ----------
__global__ void scaleshift_kernel(const float* __restrict__ g, const float* __restrict__ be, double N)
{
    int c = threadIdx.x;
    double m = g_sum[c] / N;
    double var = g_sumsq[c] / N - m * m;
    double r = 1.0 / sqrt(var + 1e-5);
    double sc = (double)g[c] * r;
    g_scale[c] = (float)sc;
    g_shift[c] = (float)((double)be[c] - m * sc);
    g_sum[c] = 0.0;
    g_sumsq[c] = 0.0;
}

// ---------------- ||codebook_k||^2 ----------------------------------------------
__global__ void cnorm_kernel(const float* __restrict__ cb)
{
    int gw = (blockIdx.x * 256 + threadIdx.x) >> 5;
    int lane = threadIdx.x & 31;
    float s = 0.f;
    const float* row = cb + (size_t)gw * ND;
    for (int d = lane; d < ND; d += 32) { float v = row[d]; s = fmaf(v, v, s); }
#pragma unroll
    for (int off = 16; off; off >>= 1) s += __shfl_xor_sync(0xffffffffu, s, off);
    if (lane == 0) g_cnorm[gw] = s;
}

// ---------------- VQ: argmin + z_q write + counts + segment sums ----------------
__global__ __launch_bounds__(256) void vq_kernel(
    const float* __restrict__ ze, const float* __restrict__ cb, float* __restrict__ zq)
{
    __shared__ float z_s[64][17];
    __shared__ float c_s[128][17];
    __shared__ int sbest[64];

    const int tid = threadIdx.x;
    const int tok0 = blockIdx.x * 64;
    const int tokg = tid >> 4;
    const int codeg = tid & 15;

    float bval[4];
    int bidx[4];
#pragma unroll
    for (int i = 0; i < 4; i++) { bval[i] = 1e30f; bidx[i] = 0x7fffffff; }

    for (int ct = 0; ct < NK; ct += 128) {
        float acc[4][8];
#pragma unroll
        for (int i = 0; i < 4; i++)
#pragma unroll
            for (int j = 0; j < 8; j++) acc[i][j] = 0.f;

        for (int d0 = 0; d0 < ND; d0 += 16) {
            __syncthreads();
            for (int idx = tid; idx < 1024; idx += 256) {
                int r = idx >> 4, dj = idx & 15;
                z_s[r][dj] = ze[(size_t)(tok0 + r) * ND + d0 + dj];
            }
            for (int idx = tid; idx < 2048; idx += 256) {
                int r = idx >> 4, dj = idx & 15;
                c_s[r][dj] = cb[(size_t)(ct + r) * ND + d0 + dj];
            }
            __syncthreads();
#pragma unroll
            for (int dj = 0; dj < 16; dj++) {
                float zr[4], cr[8];
#pragma unroll
                for (int i = 0; i < 4; i++) zr[i] = z_s[tokg * 4 + i][dj];
#pragma unroll
                for (int j = 0; j < 8; j++) cr[j] = c_s[codeg + 16 * j][dj];
#pragma unroll
                for (int i = 0; i < 4; i++)
#pragma unroll
                    for (int j = 0; j < 8; j++)
                        acc[i][j] = fmaf(zr[i], cr[j], acc[i][j]);
            }
        }
#pragma unroll
        for (int j = 0; j < 8; j++) {
            int code = ct + codeg + 16 * j;
            float cn = g_cnorm[code];
#pragma unroll
            for (int i = 0; i < 4; i++) {
                float s = fmaf(-2.f, acc[i][j], cn);
                if (s < bval[i] || (s == bval[i] && code < bidx[i])) { bval[i] = s; bidx[i] = code; }
            }
        }
    }
#pragma unroll
    for (int off = 8; off >= 1; off >>= 1) {
#pragma unroll
        for (int i = 0; i < 4; i++) {
            float ov = __shfl_xor_sync(0xffffffffu, bval[i], off);
            int oi = __shfl_xor_sync(0xffffffffu, bidx[i], off);
            if (ov < bval[i] || (ov == bval[i] && oi < bidx[i])) { bval[i] = ov; bidx[i] = oi; }
        }
    }
    if (codeg == 0) {
#pragma unroll
        for (int i = 0; i < 4; i++) sbest[tokg * 4 + i] = bidx[i];
    }
    __syncthreads();
    if (tid < 64) atomicAdd(&g_cnt[sbest[tid]], 1.0f);
    for (int e = tid; e < 64 * ND; e += 256) {
        int r = e >> 8, d = e & 255;
        int code = sbest[r];
        size_t gz = (size_t)(tok0 + r) * ND + d;
        float zev = ze[gz];
        float cbv = cb[(size_t)code * ND + d];
        zq[gz] = zev + (cbv - zev);
        atomicAdd(&g_sumcur[(size_t)code * ND + d], zev);
    }
}

// ---------------- EMA epilogue ---------------------------------------------------
__global__ void ema1_kernel(const float* __restrict__ ecs, float* __restrict__ necs)
{
    __shared__ float red[1024];
    int k = threadIdx.x;
    float ne = ecs[k] * 0.99f + 0.01f * g_cnt[k];
    necs[k] = ne;
    g_cnt[k] = 0.f;
    red[k] = ne;
    __syncthreads();
    for (int off = 512; off; off >>= 1) {
        if (k < off) red[k] += red[k + off];
        __syncthreads();
    }
    if (k == 0) g_n = red[0];
}

__global__ void ema2_kernel(const float* __restrict__ ema_w, const float* __restrict__ necs,
                            float* __restrict__ ncb)
{
    int k = blockIdx.x, d = threadIdx.x;
    float n = g_n;
    float smoothed = (necs[k] + 1e-5f) / (n + 1024.f * 1e-5f) * n;
    size_t idx = (size_t)k * ND + d;
    float nw = ema_w[idx] * 0.99f + 0.01f * g_sumcur[idx];
    ncb[idx] = nw / smoothed;
    g_sumcur[idx] = 0.f;
}

// ---------------- host launcher ---------------------------------------------------
extern "C" void kernel_launch(void* const* d_in, const int* in_sizes, int n_in,
                              void* d_out, int out_size)
{
    const float* X = (const float*)d_in[0];
    const float *W[6], *Bi[6], *G[5], *Be[5];

    bool sig = (in_sizes[3] == 256);
    if (!sig) {
        for (int i = 0; i < 6; i++) { W[i] = (const float*)d_in[1 + 2 * i]; Bi[i] = (const float*)d_in[2 + 2 * i]; }
        for (int i = 0; i < 5; i++) { G[i] = (const float*)d_in[13 + 2 * i]; Be[i] = (const float*)d_in[14 + 2 * i]; }
    } else {
        for (int i = 0; i < 5; i++) {
            W[i]  = (const float*)d_in[1 + 4 * i];
            Bi[i] = (const float*)d_in[2 + 4 * i];
            G[i]  = (const float*)d_in[3 + 4 * i];
            Be[i] = (const float*)d_in[4 + 4 * i];
        }
        W[5] = (const float*)d_in[21];
        Bi[5] = (const float*)d_in[22];
    }
    const float* codebook = (const float*)d_in[23];
    const float* ema_w    = (const float*)d_in[24];
    const float* ecs      = (const float*)d_in[25];

    float* out  = (float*)d_out;
    float* ze   = out;
    float* zq   = out + (size_t)33554432;
    float* ncb  = out + (size_t)67108864;
    float* necs = out + (size_t)67371008;

    float *bufA = nullptr, *bufB = nullptr;
    cudaGetSymbolAddress((void**)&bufA, g_bufA);
    cudaGetSymbolAddress((void**)&bufB, g_bufB);

    cudaFuncSetAttribute(convmma_kernel, cudaFuncAttributeMaxDynamicSharedMemorySize, SMEM_MMA);

    dim3 blk(256);
    conv1_kernel<<<dim3(65, 4, 32), blk>>>(X, W[0], Bi[0], bufA);
    scaleshift_kernel<<<1, 256>>>(G[0], Be[0], (double)(32.0 * 4097.0));
    wsplit_kernel<<<256, 256>>>(W[1]);
    convmma_kernel<<<dim3(32, 2, 32), blk, SMEM_MMA>>>(bufA, Bi[1], bufB, 4097, 4096, 1, TS_INT, 1);
    scaleshift_kernel<<<1, 256>>>(G[1], Be[1], (double)(32.0 * 4096.0));
    wsplit_kernel<<<256, 256>>>(W[2]);
    convmma_kernel<<<dim3(33, 2, 32), blk, SMEM_MMA>>>(bufB, Bi[2], bufA, 4096, 4097, 2, TS_INT, 1);
    scaleshift_kernel<<<1, 256>>>(G[2], Be[2], (double)(32.0 * 4097.0));
    wsplit_kernel<<<256, 256>>>(W[3]);
    convmma_kernel<<<dim3(32, 2, 32), blk, SMEM_MMA>>>(bufA, Bi[3], bufB, 4097, 4096, 1, TS_INT, 1);
    scaleshift_kernel<<<1, 256>>>(G[3], Be[3], (double)(32.0 * 4096.0));
    wsplit_kernel<<<256, 256>>>(W[4]);
    convmma_kernel<<<dim3(33, 2, 32), blk, SMEM_MMA>>>(bufB, Bi[4], bufA, 4096, 4097, 2, TS_INT, 1);
    scaleshift_kernel<<<1, 256>>>(G[4], Be[4], (double)(32.0 * 4097.0));
    wsplit_kernel<<<256, 256>>>(W[5]);
    convmma_kernel<<<dim3(32, 2, 32), blk, SMEM_MMA>>>(bufA, Bi[5], ze, 4097, 4096, 1, 4096, 0);

    cnorm_kernel<<<128, 256>>>(codebook);
    vq_kernel<<<2048, 256>>>(ze, codebook, zq);
    ema1_kernel<<<1, 1024>>>(ecs, necs);
    ema2_kernel<<<1024, 256>>>(ema_w, necs, ncb);
}

// round 8
// speedup vs baseline: 1.5603x; 1.0013x over previous
#include <cuda_runtime.h>
#include <cstdint>

#define NB 32
#define NT 4096
#define ND 256
#define NK 1024
#define TS_INT 4104        // token stride of intermediate activation buffers

// ---------------- scratch (static device globals; no allocation) ----------------
__device__ float  g_bufA[(size_t)NB * TS_INT * ND];
__device__ float  g_bufB[(size_t)NB * TS_INT * ND];
__device__ float  g_whi[(size_t)ND * 1024];     // permuted: [oc][chunk][kk][ch&7]
__device__ float  g_wlo[(size_t)ND * 1024];
__device__ double g_sum[ND];
__device__ double g_sumsq[ND];
__device__ float  g_scale[ND];
__device__ float  g_shift[ND];
__device__ float  g_cnorm[NK];
__device__ float  g_cnt[NK];
__device__ float  g_sumcur[(size_t)NK * ND];
__device__ float  g_n;

// ---------------- helpers --------------------------------------------------------
__device__ __forceinline__ uint32_t smem_u32(const void* p) {
    uint32_t a;
    asm("{ .reg .u64 t; cvta.to.shared.u64 t, %1; cvt.u32.u64 %0, t; }" : "=r"(a) : "l"(p));
    return a;
}
__device__ __forceinline__ float tf32r(float x) {
    float r;
    asm("cvt.rna.tf32.f32 %0, %1;" : "=f"(r) : "f"(x));
    return r;
}
__device__ __forceinline__ uint32_t swz(uint32_t off) { return off ^ ((off >> 3) & 0x70); }

__device__ __forceinline__ void ldm_x4(uint32_t& r0, uint32_t& r1, uint32_t& r2, uint32_t& r3, uint32_t a) {
    asm volatile("ldmatrix.sync.aligned.m8n8.x4.shared.b16 {%0,%1,%2,%3}, [%4];"
                 : "=r"(r0), "=r"(r1), "=r"(r2), "=r"(r3) : "r"(a));
}
__device__ __forceinline__ void mma8(float* c, const uint32_t* a, const uint32_t* b) {
    asm volatile("mma.sync.aligned.m16n8k8.row.col.f32.tf32.tf32.f32 "
        "{%0,%1,%2,%3}, {%4,%5,%6,%7}, {%8,%9}, {%0,%1,%2,%3};"
        : "+f"(c[0]), "+f"(c[1]), "+f"(c[2]), "+f"(c[3])
        : "r"(a[0]), "r"(a[1]), "r"(a[2]), "r"(a[3]), "r"(b[0]), "r"(b[1]));
}
#define CP_ASYNC16(dst, src) asm volatile("cp.async.cg.shared.global [%0], [%1], 16;" :: "r"(dst), "l"(src))
#define CP_COMMIT()  asm volatile("cp.async.commit_group;" ::: "memory")
#define CP_WAIT0()   asm volatile("cp.async.wait_group 0;" ::: "memory")

// smem stage: A_hi[128 rows x 128B] | A_lo | B_hi[136 rows x 32B] | B_lo
#define O_ALO 16384
#define O_BHI 32768
#define O_BLO (32768 + 4608)
#define STAGE 41984                          // 41 KB, 1024-aligned
#define O_STAT (2 * STAGE)
#define SMEM_MMA (O_STAT + 2048)

// ---------------- weight split + permute prep (per layer) -----------------------
// in: w[oc][ch][kk]  ->  out[oc][ch>>3][kk][ch&7], tf32 hi/lo split
__global__ void wsplit_kernel(const float* __restrict__ w)
{
    int i = blockIdx.x * 256 + threadIdx.x;      // 65536 = (oc, ch)
    int oc = i >> 8, ch = i & 255;
    float4 v = *(const float4*)&w[(size_t)oc * 1024 + ch * 4];
    size_t base = (size_t)oc * 1024 + (ch >> 3) * 32 + (ch & 7);
#pragma unroll
    for (int kk = 0; kk < 4; kk++) {
        float x = (&v.x)[kk];
        float hi = tf32r(x);
        g_whi[base + kk * 8] = hi;
        g_wlo[base + kk * 8] = tf32r(x - hi);
    }
}

// ============ conv D->D: pipelined mma.sync tf32 3x-split, tap-shifted B ========
// C[128 oc][128 tok]; K = 32 chunks of (8 ch x 4 taps). B fragments loaded as
// paired ldmatrix.x4 (2 n-tiles per instr); A_lo loads deferred past hi passes.
__global__ __launch_bounds__(256, 1) void convmma_kernel(
    const float* __restrict__ in, const float* __restrict__ bias,
    float* __restrict__ out, int Lin, int Lout, int pad, int tstride, int do_stats)
{
    extern __shared__ __align__(1024) char smem[];
    const int tid = threadIdx.x;
    const int wid = tid >> 5, lane = tid & 31;
    const int b = blockIdx.z, oc0 = blockIdx.y * 128, t0 = blockIdx.x * 128;
    const int ocw = (wid & 1) * 64;
    const int tokw = (wid >> 1) * 32;

    const uint32_t sb = smem_u32(smem);
    const float* xb = in + (size_t)b * TS_INT * ND;

    // A fragment bases (within stage, SW128 rows of 128B)
    uint32_t abase[4];
    {
        int ar = ocw + (lane & 7) + ((lane >> 3) & 1) * 8;
        int aq = (lane >> 4) & 1;
#pragma unroll
        for (int mt = 0; mt < 4; mt++) {
            int r = ar + mt * 16;
            abase[mt] = (uint32_t)(r * 128 + ((aq * 16) ^ ((r & 7) << 4)));
        }
    }
    // B paired-x4 per-lane row base: group g=lane>>3 -> (col16 = g&1, +8 rows = g>>1)
    const int brow0 = tokw + (lane & 7) + (((lane >> 4) & 1) << 3);
    const uint32_t bcol = (uint32_t)(((lane >> 3) & 1) << 4);

    float C[4][4][4];
#pragma unroll
    for (int mt = 0; mt < 4; mt++)
#pragma unroll
        for (int nt = 0; nt < 4; nt++)
#pragma unroll
            for (int q = 0; q < 4; q++) C[mt][nt][q] = 0.f;

    // ---- B prefetch state: thread -> (token j = tid>>1, seg h = tid&1) ---------
    const int jj = tid >> 1, hh = tid & 1;
    const int jx = 128 + (tid >> 1);             // extra rows 128..130 for tid<6
    float4 bpre0, bpre1, spre, hpre;

    // ---- prologue: stage 0 -----------------------------------------------------
    {
        const float* whp = g_whi + (size_t)oc0 * 1024;
        const float* wlp = g_wlo + (size_t)oc0 * 1024;
#pragma unroll
        for (int it = 0; it < 8; it++) {
            int idx = tid + it * 256, r = idx >> 3, ql = idx & 7, rr = r & 127;
            const float* src = ((r < 128) ? whp : wlp) + (size_t)rr * 1024 + ql * 4;
            uint32_t dst = sb + ((r < 128) ? 0u : (uint32_t)O_ALO) + swz((uint32_t)(rr * 128 + ql * 16));
            CP_ASYNC16(dst, src);
        }
        CP_COMMIT();
        int ti = t0 - pad + jj;
        bpre0 = ((unsigned)ti < (unsigned)Lin) ? *(const float4*)&xb[(size_t)ti * ND + hh * 4]
                                               : make_float4(0.f, 0.f, 0.f, 0.f);
        if (tid < 6) {
            int t2 = t0 - pad + jx;
            bpre1 = ((unsigned)t2 < (unsigned)Lin) ? *(const float4*)&xb[(size_t)t2 * ND + hh * 4]
                                                   : make_float4(0.f, 0.f, 0.f, 0.f);
        }
        spre = *(const float4*)&g_scale[hh * 4];
        hpre = *(const float4*)&g_shift[hh * 4];
    }

    for (int cc = 0; cc < 32; cc++) {
        const uint32_t su = sb + (cc & 1) * STAGE;
        char* st = smem + (cc & 1) * STAGE;

        CP_WAIT0();
        // ---- STS B from prefetch regs (BN+ReLU+split at store time) -----------
        {
            int ti = t0 - pad + jj;
            bool ok = (unsigned)ti < (unsigned)Lin;
            float4 hi4, lo4;
#pragma unroll
            for (int q = 0; q < 4; q++) {
                float v = ok ? fmaxf(fmaf((&bpre0.x)[q], (&spre.x)[q], (&hpre.x)[q]), 0.f) : 0.f;
                float h = tf32r(v);
                (&hi4.x)[q] = h; (&lo4.x)[q] = tf32r(v - h);
            }
            uint32_t byte = (uint32_t)(jj * 32 + hh * 16) ^ ((uint32_t)(jj & 4) << 2);
            *(float4*)(st + O_BHI + byte) = hi4;
            *(float4*)(st + O_BLO + byte) = lo4;
            if (tid < 6) {
                int t2 = t0 - pad + jx;
                bool ok2 = (unsigned)t2 < (unsigned)Lin;
                float4 hi2, lo2;
#pragma unroll
                for (int q = 0; q < 4; q++) {
                    float v = ok2 ? fmaxf(fmaf((&bpre1.x)[q], (&spre.x)[q], (&hpre.x)[q]), 0.f) : 0.f;
                    float h = tf32r(v);
                    (&hi2.x)[q] = h; (&lo2.x)[q] = tf32r(v - h);
                }
                uint32_t byte2 = (uint32_t)(jx * 32 + hh * 16) ^ ((uint32_t)(jx & 4) << 2);
                *(float4*)(st + O_BHI + byte2) = hi2;
                *(float4*)(st + O_BLO + byte2) = lo2;
            }
        }
        __syncthreads();      // single barrier per chunk

        // ---- prefetch chunk cc+1 (A via cp.async, B via regs) ------------------
        if (cc + 1 < 32) {
            const float* whp = g_whi + (size_t)oc0 * 1024 + (cc + 1) * 32;
            const float* wlp = g_wlo + (size_t)oc0 * 1024 + (cc + 1) * 32;
            uint32_t sd = sb + ((cc + 1) & 1) * STAGE;
#pragma unroll
            for (int it = 0; it < 8; it++) {
                int idx = tid + it * 256, r = idx >> 3, ql = idx & 7, rr = r & 127;
                const float* src = ((r < 128) ? whp : wlp) + (size_t)rr * 1024 + ql * 4;
                uint32_t dst = sd + ((r < 128) ? 0u : (uint32_t)O_ALO) + swz((uint32_t)(rr * 128 + ql * 16));
                CP_ASYNC16(dst, src);
            }
            CP_COMMIT();
            const int ch0 = (cc + 1) * 8;
            int ti = t0 - pad + jj;
            bpre0 = ((unsigned)ti < (unsigned)Lin) ? *(const float4*)&xb[(size_t)ti * ND + ch0 + hh * 4]
                                                   : make_float4(0.f, 0.f, 0.f, 0.f);
            if (tid < 6) {
                int t2 = t0 - pad + jx;
                bpre1 = ((unsigned)t2 < (unsigned)Lin) ? *(const float4*)&xb[(size_t)t2 * ND + ch0 + hh * 4]
                                                       : make_float4(0.f, 0.f, 0.f, 0.f);
            }
            spre = *(const float4*)&g_scale[ch0 + hh * 4];
            hpre = *(const float4*)&g_shift[ch0 + hh * 4];
        }

        // ---- mma on chunk cc: paired-x4 B loads, deferred A_lo -----------------
#pragma unroll
        for (int ks = 0; ks < 4; ks++) {
            uint32_t bh[4][2], bl[4][2], ah[4][4], al[4][4];
            // B: 2 paired x4 loads cover 4 n-tiles (hi), 2 more for lo
#pragma unroll
            for (int p = 0; p < 2; p++) {
                int r = brow0 + p * 16 + ks;
                uint32_t byte = ((uint32_t)(r * 32) + bcol) ^ ((uint32_t)(r & 4) << 2);
                uint32_t ad = su + O_BHI + byte;
                ldm_x4(bh[2 * p][0], bh[2 * p][1], bh[2 * p + 1][0], bh[2 * p + 1][1], ad);
                ldm_x4(bl[2 * p][0], bl[2 * p][1], bl[2 * p + 1][0], bl[2 * p + 1][1],
                       ad + (O_BLO - O_BHI));
            }
            // A hi
#pragma unroll
            for (int mt = 0; mt < 4; mt++) {
                uint32_t ad = su + (abase[mt] ^ (uint32_t)(ks << 5));
                ldm_x4(ah[mt][0], ah[mt][1], ah[mt][2], ah[mt][3], ad);
            }
            // pass 1: hi*hi
#pragma unroll
            for (int mt = 0; mt < 4; mt++)
#pragma unroll
                for (int nt = 0; nt < 4; nt++) mma8(C[mt][nt], ah[mt], bh[nt]);
            // pass 2: hi*lo
#pragma unroll
            for (int mt = 0; mt < 4; mt++)
#pragma unroll
                for (int nt = 0; nt < 4; nt++) mma8(C[mt][nt], ah[mt], bl[nt]);
            // A lo (deferred — lowers peak register pressure)
#pragma unroll
            for (int mt = 0; mt < 4; mt++) {
                uint32_t ad = su + (abase[mt] ^ (uint32_t)(ks << 5)) + O_ALO;
                ldm_x4(al[mt][0], al[mt][1], al[mt][2], al[mt][3], ad);
            }
            // pass 3: lo*hi
#pragma unroll
            for (int mt = 0; mt < 4; mt++)
#pragma unroll
                for (int nt = 0; nt < 4; nt++) mma8(C[mt][nt], al[mt], bh[nt]);
        }
    }
    __syncthreads();

    // ---- epilogue: bias + BN stats + smem transpose + coalesced store ----------
    double* ssumS = (double*)(smem + O_STAT);
    double* ssqS  = (double*)(smem + O_STAT + 1024);
    if (tid < 128) { ssumS[tid] = 0.0; ssqS[tid] = 0.0; }
    float* eb = (float*)smem;                 // [128 tok][132 oc]
    __syncthreads();

#pragma unroll
    for (int mt = 0; mt < 4; mt++) {
#pragma unroll
        for (int h = 0; h < 2; h++) {
            int ocl = ocw + mt * 16 + (lane >> 2) + h * 8;
            float bv = bias[oc0 + ocl];
            double s = 0.0, q = 0.0;
#pragma unroll
            for (int nt = 0; nt < 4; nt++) {
#pragma unroll
                for (int p = 0; p < 2; p++) {
                    int n = tokw + nt * 8 + (lane & 3) * 2 + p;
                    float v = C[mt][nt][h * 2 + p] + bv;
                    eb[n * 132 + ocl] = v;
                    if (do_stats && (t0 + n < Lout)) { double d = (double)v; s += d; q += d * d; }
                }
            }
            if (do_stats) { atomicAdd(&ssumS[ocl], s); atomicAdd(&ssqS[ocl], q); }
        }
    }
    __syncthreads();

    for (int idx = tid; idx < 4096; idx += 256) {
        int r = idx >> 5, ql = idx & 31;
        if (t0 + r < Lout)
            *(float4*)&out[((size_t)b * tstride + t0 + r) * ND + oc0 + ql * 4] =
                *(float4*)&eb[r * 132 + ql * 4];
    }
    if (do_stats && tid < 128) {
        atomicAdd(&g_sum[oc0 + tid], ssumS[tid]);
        atomicAdd(&g_sumsq[oc0 + tid], ssqS[tid]);
    }
}

// ---------------- layer 1: conv 12 -> 256, k=4, pad=2 (scalar; tiny K) ----------
__global__ __launch_bounds__(256) void conv1_kernel(
    const float* __restrict__ x, const float* __restrict__ w,
    const float* __restrict__ bias, float* __restrict__ out)
{
    __shared__ float in_s[12][68];
    __shared__ float w_s[64][49];
    __shared__ float o_s[64][65];
    __shared__ double ssum[64], ssq[64];

    const int tid = threadIdx.x;
    const int b = blockIdx.z, oc0 = blockIdx.y * 64, t0 = blockIdx.x * 64;
    const int ocl = tid & 63, tg = tid >> 6, tbase = tg * 16;
    const int Lout = 4097;

    for (int idx = tid; idx < 12 * 67; idx += 256) {
        int j = idx / 12, c = idx - j * 12;
        int ip = t0 - 2 + j;
        in_s[c][j] = ((unsigned)ip < 4096u) ? x[((size_t)b * NT + ip) * 12 + c] : 0.f;
    }
    for (int idx = tid; idx < 64 * 48; idx += 256) {
        int oc = idx / 48, r = idx - oc * 48;
        w_s[oc][r] = w[(size_t)(oc0 + oc) * 48 + r];
    }
    __syncthreads();

    float acc[16];
#pragma unroll
    for (int u = 0; u < 16; u++) acc[u] = 0.f;
#pragma unroll
    for (int c = 0; c < 12; c++) {
        float v[19];
#pragma unroll
        for (int u = 0; u < 19; u++) v[u] = in_s[c][tbase + u];
        float w0 = w_s[ocl][c * 4 + 0], w1 = w_s[ocl][c * 4 + 1];
        float w2 = w_s[ocl][c * 4 + 2], w3 = w_s[ocl][c * 4 + 3];
#pragma unroll
        for (int u = 0; u < 16; u++)
            acc[u] = fmaf(w3, v[u + 3], fmaf(w2, v[u + 2], fmaf(w1, v[u + 1], fmaf(w0, v[u], acc[u]))));
    }
    const float bv = bias[oc0 + ocl];
#pragma unroll
    for (int u = 0; u < 16; u++) acc[u] += bv;

    {
        double s = 0.0, q = 0.0;
#pragma unroll
        for (int u = 0; u < 16; u++)
            if (t0 + tbase + u < Lout) { double a = (double)acc[u]; s += a; q += a * a; }
        __syncthreads();
        if (tid < 64) { ssum[tid] = 0.0; ssq[tid] = 0.0; }
        __syncthreads();
        atomicAdd(&ssum[ocl], s);
        atomicAdd(&ssq[ocl], q);
        __syncthreads();
        if (tid < 64) {
            atomicAdd(&g_sum[oc0 + tid], ssum[tid]);
            atomicAdd(&g_sumsq[oc0 + tid], ssq[tid]);
        }
    }

    __syncthreads();
#pragma unroll
    for (int u = 0; u < 16; u++) o_s[ocl][tbase + u] = acc[u];
    __syncthreads();
    float* ob = out + ((size_t)b * TS_INT + t0) * ND + oc0;
    for (int idx = tid; idx < 4096; idx += 256) {
        int t = idx >> 6, oc = idx & 63;
        if (t0 + t < Lout) ob[(size_t)t * ND + oc] = o_s[oc][t];
    }
}

// ---------------- BN stats -> scale/shift for next layer; resets stats ----------
__global__ void scaleshift_kernel(const float* __restrict__ g, const float* __restrict__ be, double N)
{
    int c = threadIdx.x;
    double m = g_sum[c] / N;
    double var = g_sumsq[c] / N - m * m;
    double r = 1.0 / sqrt(var + 1e-5);
    double sc = (double)g[c] * r;
    g_scale[c] = (float)sc;
    g_shift[c] = (float)((double)be[c] - m * sc);
    g_sum[c] = 0.0;
    g_sumsq[c] = 0.0;
}

// ---------------- ||codebook_k||^2 ----------------------------------------------
__global__ void cnorm_kernel(const float* __restrict__ cb)
{
    int gw = (blockIdx.x * 256 + threadIdx.x) >> 5;
    int lane = threadIdx.x & 31;
    float s = 0.f;
    const float* row = cb + (size_t)gw * ND;
    for (int d = lane; d < ND; d += 32) { float v = row[d]; s = fmaf(v, v, s); }
#pragma unroll
    for (int off = 16; off; off >>= 1) s += __shfl_xor_sync(0xffffffffu, s, off);
    if (lane == 0) g_cnorm[gw] = s;
}

// ---------------- VQ: argmin + z_q write + counts + segment sums ----------------
__global__ __launch_bounds__(256) void vq_kernel(
    const float* __restrict__ ze, const float* __restrict__ cb, float* __restrict__ zq)
{
    __shared__ float z_s[64][17];
    __shared__ float c_s[128][17];
    __shared__ int sbest[64];

    const int tid = threadIdx.x;
    const int tok0 = blockIdx.x * 64;
    const int tokg = tid >> 4;
    const int codeg = tid & 15;

    float bval[4];
    int bidx[4];
#pragma unroll
    for (int i = 0; i < 4; i++) { bval[i] = 1e30f; bidx[i] = 0x7fffffff; }

    for (int ct = 0; ct < NK; ct += 128) {
        float acc[4][8];
#pragma unroll
        for (int i = 0; i < 4; i++)
#pragma unroll
            for (int j = 0; j < 8; j++) acc[i][j] = 0.f;

        for (int d0 = 0; d0 < ND; d0 += 16) {
            __syncthreads();
            for (int idx = tid; idx < 1024; idx += 256) {
                int r = idx >> 4, dj = idx & 15;
                z_s[r][dj] = ze[(size_t)(tok0 + r) * ND + d0 + dj];
            }
            for (int idx = tid; idx < 2048; idx += 256) {
                int r = idx >> 4, dj = idx & 15;
                c_s[r][dj] = cb[(size_t)(ct + r) * ND + d0 + dj];
            }
            __syncthreads();
#pragma unroll
            for (int dj = 0; dj < 16; dj++) {
                float zr[4], cr[8];
#pragma unroll
                for (int i = 0; i < 4; i++) zr[i] = z_s[tokg * 4 + i][dj];
#pragma unroll
                for (int j = 0; j < 8; j++) cr[j] = c_s[codeg + 16 * j][dj];
#pragma unroll
                for (int i = 0; i < 4; i++)
#pragma unroll
                    for (int j = 0; j < 8; j++)
                        acc[i][j] = fmaf(zr[i], cr[j], acc[i][j]);
            }
        }
#pragma unroll
        for (int j = 0; j < 8; j++) {
            int code = ct + codeg + 16 * j;
            float cn = g_cnorm[code];
#pragma unroll
            for (int i = 0; i < 4; i++) {
                float s = fmaf(-2.f, acc[i][j], cn);
                if (s < bval[i] || (s == bval[i] && code < bidx[i])) { bval[i] = s; bidx[i] = code; }
            }
        }
    }
#pragma unroll
    for (int off = 8; off >= 1; off >>= 1) {
#pragma unroll
        for (int i = 0; i < 4; i++) {
            float ov = __shfl_xor_sync(0xffffffffu, bval[i], off);
            int oi = __shfl_xor_sync(0xffffffffu, bidx[i], off);
            if (ov < bval[i] || (ov == bval[i] && oi < bidx[i])) { bval[i] = ov; bidx[i] = oi; }
        }
    }
    if (codeg == 0) {
#pragma unroll
        for (int i = 0; i < 4; i++) sbest[tokg * 4 + i] = bidx[i];
    }
    __syncthreads();
    if (tid < 64) atomicAdd(&g_cnt[sbest[tid]], 1.0f);
    for (int e = tid; e < 64 * ND; e += 256) {
        int r = e >> 8, d = e & 255;
        int code = sbest[r];
        size_t gz = (size_t)(tok0 + r) * ND + d;
        float zev = ze[gz];
        float cbv = cb[(size_t)code * ND + d];
        zq[gz] = zev + (cbv - zev);
        atomicAdd(&g_sumcur[(size_t)code * ND + d], zev);
    }
}

// ---------------- EMA epilogue ---------------------------------------------------
__global__ void ema1_kernel(const float* __restrict__ ecs, float* __restrict__ necs)
{
    __shared__ float red[1024];
    int k = threadIdx.x;
    float ne = ecs[k] * 0.99f + 0.01f * g_cnt[k];
    necs[k] = ne;
    g_cnt[k] = 0.f;
    red[k] = ne;
    __syncthreads();
    for (int off = 512; off; off >>= 1) {
        if (k < off) red[k] += red[k + off];
        __syncthreads();
    }
    if (k == 0) g_n = red[0];
}

__global__ void ema2_kernel(const float* __restrict__ ema_w, const float* __restrict__ necs,
                            float* __restrict__ ncb)
{
    int k = blockIdx.x, d = threadIdx.x;
    float n = g_n;
    float smoothed = (necs[k] + 1e-5f) / (n + 1024.f * 1e-5f) * n;
    size_t idx = (size_t)k * ND + d;
    float nw = ema_w[idx] * 0.99f + 0.01f * g_sumcur[idx];
    ncb[idx] = nw / smoothed;
    g_sumcur[idx] = 0.f;
}

// ---------------- host launcher ---------------------------------------------------
extern "C" void kernel_launch(void* const* d_in, const int* in_sizes, int n_in,
                              void* d_out, int out_size)
{
    const float* X = (const float*)d_in[0];
    const float *W[6], *Bi[6], *G[5], *Be[5];

    bool sig = (in_sizes[3] == 256);
    if (!sig) {
        for (int i = 0; i < 6; i++) { W[i] = (const float*)d_in[1 + 2 * i]; Bi[i] = (const float*)d_in[2 + 2 * i]; }
        for (int i = 0; i < 5; i++) { G[i] = (const float*)d_in[13 + 2 * i]; Be[i] = (const float*)d_in[14 + 2 * i]; }
    } else {
        for (int i = 0; i < 5; i++) {
            W[i]  = (const float*)d_in[1 + 4 * i];
            Bi[i] = (const float*)d_in[2 + 4 * i];
            G[i]  = (const float*)d_in[3 + 4 * i];
            Be[i] = (const float*)d_in[4 + 4 * i];
        }
        W[5] = (const float*)d_in[21];
        Bi[5] = (const float*)d_in[22];
    }
    const float* codebook = (const float*)d_in[23];
    const float* ema_w    = (const float*)d_in[24];
    const float* ecs      = (const float*)d_in[25];

    float* out  = (float*)d_out;
    float* ze   = out;
    float* zq   = out + (size_t)33554432;
    float* ncb  = out + (size_t)67108864;
    float* necs = out + (size_t)67371008;

    float *bufA = nullptr, *bufB = nullptr;
    cudaGetSymbolAddress((void**)&bufA, g_bufA);
    cudaGetSymbolAddress((void**)&bufB, g_bufB);

    cudaFuncSetAttribute(convmma_kernel, cudaFuncAttributeMaxDynamicSharedMemorySize, SMEM_MMA);

    dim3 blk(256);
    conv1_kernel<<<dim3(65, 4, 32), blk>>>(X, W[0], Bi[0], bufA);
    scaleshift_kernel<<<1, 256>>>(G[0], Be[0], (double)(32.0 * 4097.0));
    wsplit_kernel<<<256, 256>>>(W[1]);
    convmma_kernel<<<dim3(32, 2, 32), blk, SMEM_MMA>>>(bufA, Bi[1], bufB, 4097, 4096, 1, TS_INT, 1);
    scaleshift_kernel<<<1, 256>>>(G[1], Be[1], (double)(32.0 * 4096.0));
    wsplit_kernel<<<256, 256>>>(W[2]);
    convmma_kernel<<<dim3(33, 2, 32), blk, SMEM_MMA>>>(bufB, Bi[2], bufA, 4096, 4097, 2, TS_INT, 1);
    scaleshift_kernel<<<1, 256>>>(G[2], Be[2], (double)(32.0 * 4097.0));
    wsplit_kernel<<<256, 256>>>(W[3]);
    convmma_kernel<<<dim3(32, 2, 32), blk, SMEM_MMA>>>(bufA, Bi[3], bufB, 4097, 4096, 1, TS_INT, 1);
    scaleshift_kernel<<<1, 256>>>(G[3], Be[3], (double)(32.0 * 4096.0));
    wsplit_kernel<<<256, 256>>>(W[4]);
    convmma_kernel<<<dim3(33, 2, 32), blk, SMEM_MMA>>>(bufB, Bi[4], bufA, 4096, 4097, 2, TS_INT, 1);
    scaleshift_kernel<<<1, 256>>>(G[4], Be[4], (double)(32.0 * 4097.0));
    wsplit_kernel<<<256, 256>>>(W[5]);
    convmma_kernel<<<dim3(32, 2, 32), blk, SMEM_MMA>>>(bufA, Bi[5], ze, 4097, 4096, 1, 4096, 0);

    cnorm_kernel<<<128, 256>>>(codebook);
    vq_kernel<<<2048, 256>>>(ze, codebook, zq);
    ema1_kernel<<<1, 1024>>>(ecs, necs);
    ema2_kernel<<<1024, 256>>>(ema_w, necs, ncb);
}

// round 9
// speedup vs baseline: 1.8284x; 1.1718x over previous
#include <cuda_runtime.h>
#include <cstdint>

#define NB 32
#define NT 4096
#define ND 256
#define NK 1024
#define TS_INT 4104        // token stride of intermediate activation buffers

// ---------------- scratch (static device globals; no allocation) ----------------
__device__ float  g_bufA[(size_t)NB * TS_INT * ND];
__device__ float  g_bufB[(size_t)NB * TS_INT * ND];
__device__ float  g_whi[(size_t)ND * 1024];     // permuted: [oc][chunk][kk][ch&7]
__device__ float  g_wlo[(size_t)ND * 1024];
__device__ double g_sum[ND];
__device__ double g_sumsq[ND];
__device__ float  g_scale[ND];
__device__ float  g_shift[ND];
__device__ float  g_cnorm[NK];
__device__ float  g_cnt[NK];
__device__ float  g_sumcur[(size_t)NK * ND];
__device__ float  g_n;

// ---------------- helpers --------------------------------------------------------
__device__ __forceinline__ uint32_t smem_u32(const void* p) {
    uint32_t a;
    asm("{ .reg .u64 t; cvta.to.shared.u64 t, %1; cvt.u32.u64 %0, t; }" : "=r"(a) : "l"(p));
    return a;
}
__device__ __forceinline__ float tf32r(float x) {
    float r;
    asm("cvt.rna.tf32.f32 %0, %1;" : "=f"(r) : "f"(x));
    return r;
}
__device__ __forceinline__ uint32_t swz(uint32_t off) { return off ^ ((off >> 3) & 0x70); }

__device__ __forceinline__ void ldm_x4(uint32_t& r0, uint32_t& r1, uint32_t& r2, uint32_t& r3, uint32_t a) {
    asm volatile("ldmatrix.sync.aligned.m8n8.x4.shared.b16 {%0,%1,%2,%3}, [%4];"
                 : "=r"(r0), "=r"(r1), "=r"(r2), "=r"(r3) : "r"(a));
}
__device__ __forceinline__ void mma8(float* c, const uint32_t* a, const uint32_t* b) {
    asm volatile("mma.sync.aligned.m16n8k8.row.col.f32.tf32.tf32.f32 "
        "{%0,%1,%2,%3}, {%4,%5,%6,%7}, {%8,%9}, {%0,%1,%2,%3};"
        : "+f"(c[0]), "+f"(c[1]), "+f"(c[2]), "+f"(c[3])
        : "r"(a[0]), "r"(a[1]), "r"(a[2]), "r"(a[3]), "r"(b[0]), "r"(b[1]));
}
#define CP_ASYNC16(dst, src) asm volatile("cp.async.cg.shared.global [%0], [%1], 16;" :: "r"(dst), "l"(src))
#define CP_COMMIT()  asm volatile("cp.async.commit_group;" ::: "memory")
#define CP_WAIT0()   asm volatile("cp.async.wait_group 0;" ::: "memory")

// smem stage: A_hi[128 rows x 128B] | A_lo | B_hi[72 rows x 32B] | B_lo
#define O_ALO 16384
#define O_BHI 32768
#define O_BLO (32768 + 2304)
#define STAGE 37888                          // 37 KB, 1024-aligned
#define O_STAT (2 * STAGE)
#define SMEM_MMA (O_STAT + 2048)

// ---------------- weight split + permute prep (per layer) -----------------------
// in: w[oc][ch][kk]  ->  out[oc][ch>>3][kk][ch&7], tf32 hi/lo split
__global__ void wsplit_kernel(const float* __restrict__ w)
{
    int i = blockIdx.x * 256 + threadIdx.x;      // 65536 = (oc, ch)
    int oc = i >> 8, ch = i & 255;
    float4 v = *(const float4*)&w[(size_t)oc * 1024 + ch * 4];
    size_t base = (size_t)oc * 1024 + (ch >> 3) * 32 + (ch & 7);
#pragma unroll
    for (int kk = 0; kk < 4; kk++) {
        float x = (&v.x)[kk];
        float hi = tf32r(x);
        g_whi[base + kk * 8] = hi;
        g_wlo[base + kk * 8] = tf32r(x - hi);
    }
}

// ============ conv D->D: mma.sync tf32 3x-split, 2 CTAs/SM for phase overlap ====
// CTA tile: 128 oc x 64 tok, 8 warps of 32x32. K = 32 chunks of (8 ch x 4 taps).
__global__ __launch_bounds__(256, 2) void convmma_kernel(
    const float* __restrict__ in, const float* __restrict__ bias,
    float* __restrict__ out, int Lin, int Lout, int pad, int tstride, int do_stats)
{
    extern __shared__ __align__(1024) char smem[];
    const int tid = threadIdx.x;
    const int wid = tid >> 5, lane = tid & 31;
    const int b = blockIdx.z, oc0 = blockIdx.y * 128, t0 = blockIdx.x * 64;
    const int ocw = (wid & 3) * 32;          // warp oc base within CTA tile
    const int tokw = (wid >> 2) * 32;        // warp tok base within CTA tile

    const uint32_t sb = smem_u32(smem);
    const float* xb = in + (size_t)b * TS_INT * ND;

    // A fragment bases (within stage, SW128 rows of 128B); mt in {0,1}
    uint32_t abase[2];
    {
        int ar = ocw + (lane & 7) + ((lane >> 3) & 1) * 8;
        int aq = (lane >> 4) & 1;
#pragma unroll
        for (int mt = 0; mt < 2; mt++) {
            int r = ar + mt * 16;
            abase[mt] = (uint32_t)(r * 128 + ((aq * 16) ^ ((r & 7) << 4)));
        }
    }
    // B paired-x4 per-lane row base: group g=lane>>3 -> (col16 = g&1, +8 rows = g>>1)
    const int brow0 = tokw + (lane & 7) + (((lane >> 4) & 1) << 3);
    const uint32_t bcol = (uint32_t)(((lane >> 3) & 1) << 4);

    float C[2][4][4];
#pragma unroll
    for (int mt = 0; mt < 2; mt++)
#pragma unroll
        for (int nt = 0; nt < 4; nt++)
#pragma unroll
            for (int q = 0; q < 4; q++) C[mt][nt][q] = 0.f;

    // ---- B prefetch state: threads 0..133 -> (token j = tid>>1, seg h = tid&1) --
    const int jj = tid >> 1, hh = tid & 1;
    const bool bact = (tid < 134);               // rows 0..66 (64 + 3 halo)
    float4 bpre0, spre, hpre;

    // ---- prologue: stage 0 -----------------------------------------------------
    {
        const float* whp = g_whi + (size_t)oc0 * 1024;
        const float* wlp = g_wlo + (size_t)oc0 * 1024;
#pragma unroll
        for (int it = 0; it < 8; it++) {
            int idx = tid + it * 256, r = idx >> 3, ql = idx & 7, rr = r & 127;
            const float* src = ((r < 128) ? whp : wlp) + (size_t)rr * 1024 + ql * 4;
            uint32_t dst = sb + ((r < 128) ? 0u : (uint32_t)O_ALO) + swz((uint32_t)(rr * 128 + ql * 16));
            CP_ASYNC16(dst, src);
        }
        CP_COMMIT();
        if (bact) {
            int ti = t0 - pad + jj;
            bpre0 = ((unsigned)ti < (unsigned)Lin) ? *(const float4*)&xb[(size_t)ti * ND + hh * 4]
                                                   : make_float4(0.f, 0.f, 0.f, 0.f);
            spre = *(const float4*)&g_scale[hh * 4];
            hpre = *(const float4*)&g_shift[hh * 4];
        }
    }

    for (int cc = 0; cc < 32; cc++) {
        const uint32_t su = sb + (cc & 1) * STAGE;
        char* st = smem + (cc & 1) * STAGE;

        CP_WAIT0();
        // ---- STS B from prefetch regs (BN+ReLU+split at store time) -----------
        if (bact) {
            int ti = t0 - pad + jj;
            bool ok = (unsigned)ti < (unsigned)Lin;
            float4 hi4, lo4;
#pragma unroll
            for (int q = 0; q < 4; q++) {
                float v = ok ? fmaxf(fmaf((&bpre0.x)[q], (&spre.x)[q], (&hpre.x)[q]), 0.f) : 0.f;
                float h = tf32r(v);
                (&hi4.x)[q] = h; (&lo4.x)[q] = tf32r(v - h);
            }
            uint32_t byte = (uint32_t)(jj * 32 + hh * 16) ^ ((uint32_t)(jj & 4) << 2);
            *(float4*)(st + O_BHI + byte) = hi4;
            *(float4*)(st + O_BLO + byte) = lo4;
        }
        __syncthreads();      // single barrier per chunk

        // ---- prefetch chunk cc+1 (A via cp.async, B via regs) ------------------
        if (cc + 1 < 32) {
            const float* whp = g_whi + (size_t)oc0 * 1024 + (cc + 1) * 32;
            const float* wlp = g_wlo + (size_t)oc0 * 1024 + (cc + 1) * 32;
            uint32_t sd = sb + ((cc + 1) & 1) * STAGE;
#pragma unroll
            for (int it = 0; it < 8; it++) {
                int idx = tid + it * 256, r = idx >> 3, ql = idx & 7, rr = r & 127;
                const float* src = ((r < 128) ? whp : wlp) + (size_t)rr * 1024 + ql * 4;
                uint32_t dst = sd + ((r < 128) ? 0u : (uint32_t)O_ALO) + swz((uint32_t)(rr * 128 + ql * 16));
                CP_ASYNC16(dst, src);
            }
            CP_COMMIT();
            if (bact) {
                const int ch0 = (cc + 1) * 8;
                int ti = t0 - pad + jj;
                bpre0 = ((unsigned)ti < (unsigned)Lin) ? *(const float4*)&xb[(size_t)ti * ND + ch0 + hh * 4]
                                                       : make_float4(0.f, 0.f, 0.f, 0.f);
                spre = *(const float4*)&g_scale[ch0 + hh * 4];
                hpre = *(const float4*)&g_shift[ch0 + hh * 4];
            }
        }

        // ---- mma on chunk cc: paired-x4 B loads, deferred A_lo -----------------
#pragma unroll
        for (int ks = 0; ks < 4; ks++) {
            uint32_t bh[4][2], bl[4][2], ah[2][4], al[2][4];
#pragma unroll
            for (int p = 0; p < 2; p++) {
                int r = brow0 + p * 16 + ks;
                uint32_t byte = ((uint32_t)(r * 32) + bcol) ^ ((uint32_t)(r & 4) << 2);
                uint32_t ad = su + O_BHI + byte;
                ldm_x4(bh[2 * p][0], bh[2 * p][1], bh[2 * p + 1][0], bh[2 * p + 1][1], ad);
                ldm_x4(bl[2 * p][0], bl[2 * p][1], bl[2 * p + 1][0], bl[2 * p + 1][1],
                       ad + (O_BLO - O_BHI));
            }
#pragma unroll
            for (int mt = 0; mt < 2; mt++) {
                uint32_t ad = su + (abase[mt] ^ (uint32_t)(ks << 5));
                ldm_x4(ah[mt][0], ah[mt][1], ah[mt][2], ah[mt][3], ad);
            }
            // pass 1: hi*hi
#pragma unroll
            for (int mt = 0; mt < 2; mt++)
#pragma unroll
                for (int nt = 0; nt < 4; nt++) mma8(C[mt][nt], ah[mt], bh[nt]);
            // pass 2: hi*lo
#pragma unroll
            for (int mt = 0; mt < 2; mt++)
#pragma unroll
                for (int nt = 0; nt < 4; nt++) mma8(C[mt][nt], ah[mt], bl[nt]);
            // A lo (deferred)
#pragma unroll
            for (int mt = 0; mt < 2; mt++) {
                uint32_t ad = su + (abase[mt] ^ (uint32_t)(ks << 5)) + O_ALO;
                ldm_x4(al[mt][0], al[mt][1], al[mt][2], al[mt][3], ad);
            }
            // pass 3: lo*hi
#pragma unroll
            for (int mt = 0; mt < 2; mt++)
#pragma unroll
                for (int nt = 0; nt < 4; nt++) mma8(C[mt][nt], al[mt], bh[nt]);
        }
    }
    __syncthreads();

    // ---- epilogue: bias + BN stats + smem transpose + coalesced store ----------
    double* ssumS = (double*)(smem + O_STAT);
    double* ssqS  = (double*)(smem + O_STAT + 1024);
    if (tid < 128) { ssumS[tid] = 0.0; ssqS[tid] = 0.0; }
    float* eb = (float*)smem;                 // [64 tok][132 oc]
    __syncthreads();

#pragma unroll
    for (int mt = 0; mt < 2; mt++) {
#pragma unroll
        for (int h = 0; h < 2; h++) {
            int ocl = ocw + mt * 16 + (lane >> 2) + h * 8;
            float bv = bias[oc0 + ocl];
            double s = 0.0, q = 0.0;
#pragma unroll
            for (int nt = 0; nt < 4; nt++) {
#pragma unroll
                for (int p = 0; p < 2; p++) {
                    int n = tokw + nt * 8 + (lane & 3) * 2 + p;
                    float v = C[mt][nt][h * 2 + p] + bv;
                    eb[n * 132 + ocl] = v;
                    if (do_stats && (t0 + n < Lout)) { double d = (double)v; s += d; q += d * d; }
                }
            }
            if (do_stats) { atomicAdd(&ssumS[ocl], s); atomicAdd(&ssqS[ocl], q); }
        }
    }
    __syncthreads();

    for (int idx = tid; idx < 2048; idx += 256) {
        int r = idx >> 5, ql = idx & 31;
        if (t0 + r < Lout)
            *(float4*)&out[((size_t)b * tstride + t0 + r) * ND + oc0 + ql * 4] =
                *(float4*)&eb[r * 132 + ql * 4];
    }
    if (do_stats && tid < 128) {
        atomicAdd(&g_sum[oc0 + tid], ssumS[tid]);
        atomicAdd(&g_sumsq[oc0 + tid], ssqS[tid]);
    }
}

// ---------------- layer 1: conv 12 -> 256, k=4, pad=2 (scalar; tiny K) ----------
__global__ __launch_bounds__(256) void conv1_kernel(
    const float* __restrict__ x, const float* __restrict__ w,
    const float* __restrict__ bias, float* __restrict__ out)
{
    __shared__ float in_s[12][68];
    __shared__ float w_s[64][49];
    __shared__ float o_s[64][65];
    __shared__ double ssum[64], ssq[64];

    const int tid = threadIdx.x;
    const int b = blockIdx.z, oc0 = blockIdx.y * 64, t0 = blockIdx.x * 64;
    const int ocl = tid & 63, tg = tid >> 6, tbase = tg * 16;
    const int Lout = 4097;

    for (int idx = tid; idx < 12 * 67; idx += 256) {
        int j = idx / 12, c = idx - j * 12;
        int ip = t0 - 2 + j;
        in_s[c][j] = ((unsigned)ip < 4096u) ? x[((size_t)b * NT + ip) * 12 + c] : 0.f;
    }
    for (int idx = tid; idx < 64 * 48; idx += 256) {
        int oc = idx / 48, r = idx - oc * 48;
        w_s[oc][r] = w[(size_t)(oc0 + oc) * 48 + r];
    }
    __syncthreads();

    float acc[16];
#pragma unroll
    for (int u = 0; u < 16; u++) acc[u] = 0.f;
#pragma unroll
    for (int c = 0; c < 12; c++) {
        float v[19];
#pragma unroll
        for (int u = 0; u < 19; u++) v[u] = in_s[c][tbase + u];
        float w0 = w_s[ocl][c * 4 + 0], w1 = w_s[ocl][c * 4 + 1];
        float w2 = w_s[ocl][c * 4 + 2], w3 = w_s[ocl][c * 4 + 3];
#pragma unroll
        for (int u = 0; u < 16; u++)
            acc[u] = fmaf(w3, v[u + 3], fmaf(w2, v[u + 2], fmaf(w1, v[u + 1], fmaf(w0, v[u], acc[u]))));
    }
    const float bv = bias[oc0 + ocl];
#pragma unroll
    for (int u = 0; u < 16; u++) acc[u] += bv;

    {
        double s = 0.0, q = 0.0;
#pragma unroll
        for (int u = 0; u < 16; u++)
            if (t0 + tbase + u < Lout) { double a = (double)acc[u]; s += a; q += a * a; }
        __syncthreads();
        if (tid < 64) { ssum[tid] = 0.0; ssq[tid] = 0.0; }
        __syncthreads();
        atomicAdd(&ssum[ocl], s);
        atomicAdd(&ssq[ocl], q);
        __syncthreads();
        if (tid < 64) {
            atomicAdd(&g_sum[oc0 + tid], ssum[tid]);
            atomicAdd(&g_sumsq[oc0 + tid], ssq[tid]);
        }
    }

    __syncthreads();
#pragma unroll
    for (int u = 0; u < 16; u++) o_s[ocl][tbase + u] = acc[u];
    __syncthreads();
    float* ob = out + ((size_t)b * TS_INT + t0) * ND + oc0;
    for (int idx = tid; idx < 4096; idx += 256) {
        int t = idx >> 6, oc = idx & 63;
        if (t0 + t < Lout) ob[(size_t)t * ND + oc] = o_s[oc][t];
    }
}

// ---------------- BN stats -> scale/shift for next layer; resets stats ----------
__global__ void scaleshift_kernel(const float* __restrict__ g, const float* __restrict__ be, double N)
{
    int c = threadIdx.x;
    double m = g_sum[c] / N;
    double var = g_sumsq[c] / N - m * m;
    double r = 1.0 / sqrt(var + 1e-5);
    double sc = (double)g[c] * r;
    g_scale[c] = (float)sc;
    g_shift[c] = (float)((double)be[c] - m * sc);
    g_sum[c] = 0.0;
    g_sumsq[c] = 0.0;
}

// ---------------- ||codebook_k||^2 ----------------------------------------------
__global__ void cnorm_kernel(const float* __restrict__ cb)
{
    int gw = (blockIdx.x * 256 + threadIdx.x) >> 5;
    int lane = threadIdx.x & 31;
    float s = 0.f;
    const float* row = cb + (size_t)gw * ND;
    for (int d = lane; d < ND; d += 32) { float v = row[d]; s = fmaf(v, v, s); }
#pragma unroll
    for (int off = 16; off; off >>= 1) s += __shfl_xor_sync(0xffffffffu, s, off);
    if (lane == 0) g_cnorm[gw] = s;
}

// ---------------- VQ: argmin + z_q write + counts + segment sums ----------------
__global__ __launch_bounds__(256) void vq_kernel(
    const float* __restrict__ ze, const float* __restrict__ cb, float* __restrict__ zq)
{
    __shared__ float z_s[64][17];
    __shared__ float c_s[128][17];
    __shared__ int sbest[64];

    const int tid = threadIdx.x;
    const int tok0 = blockIdx.x * 64;
    const int tokg = tid >> 4;
    const int codeg = tid & 15;

    float bval[4];
    int bidx[4];
#pragma unroll
    for (int i = 0; i < 4; i++) { bval[i] = 1e30f; bidx[i] = 0x7fffffff; }

    for (int ct = 0; ct < NK; ct += 128) {
        float acc[4][8];
#pragma unroll
        for (int i = 0; i < 4; i++)
#pragma unroll
            for (int j = 0; j < 8; j++) acc[i][j] = 0.f;

        for (int d0 = 0; d0 < ND; d0 += 16) {
            __syncthreads();
            for (int idx = tid; idx < 1024; idx += 256) {
                int r = idx >> 4, dj = idx & 15;
                z_s[r][dj] = ze[(size_t)(tok0 + r) * ND + d0 + dj];
            }
            for (int idx = tid; idx < 2048; idx += 256) {
                int r = idx >> 4, dj = idx & 15;
                c_s[r][dj] = cb[(size_t)(ct + r) * ND + d0 + dj];
            }
            __syncthreads();
#pragma unroll
            for (int dj = 0; dj < 16; dj++) {
                float zr[4], cr[8];
#pragma unroll
                for (int i = 0; i < 4; i++) zr[i] = z_s[tokg * 4 + i][dj];
#pragma unroll
                for (int j = 0; j < 8; j++) cr[j] = c_s[codeg + 16 * j][dj];
#pragma unroll
                for (int i = 0; i < 4; i++)
#pragma unroll
                    for (int j = 0; j < 8; j++)
                        acc[i][j] = fmaf(zr[i], cr[j], acc[i][j]);
            }
        }
#pragma unroll
        for (int j = 0; j < 8; j++) {
            int code = ct + codeg + 16 * j;
            float cn = g_cnorm[code];
#pragma unroll
            for (int i = 0; i < 4; i++) {
                float s = fmaf(-2.f, acc[i][j], cn);
                if (s < bval[i] || (s == bval[i] && code < bidx[i])) { bval[i] = s; bidx[i] = code; }
            }
        }
    }
#pragma unroll
    for (int off = 8; off >= 1; off >>= 1) {
#pragma unroll
        for (int i = 0; i < 4; i++) {
            float ov = __shfl_xor_sync(0xffffffffu, bval[i], off);
            int oi = __shfl_xor_sync(0xffffffffu, bidx[i], off);
            if (ov < bval[i] || (ov == bval[i] && oi < bidx[i])) { bval[i] = ov; bidx[i] = oi; }
        }
    }
    if (codeg == 0) {
#pragma unroll
        for (int i = 0; i < 4; i++) sbest[tokg * 4 + i] = bidx[i];
    }
    __syncthreads();
    if (tid < 64) atomicAdd(&g_cnt[sbest[tid]], 1.0f);
    for (int e = tid; e < 64 * ND; e += 256) {
        int r = e >> 8, d = e & 255;
        int code = sbest[r];
        size_t gz = (size_t)(tok0 + r) * ND + d;
        float zev = ze[gz];
        float cbv = cb[(size_t)code * ND + d];
        zq[gz] = zev + (cbv - zev);
        atomicAdd(&g_sumcur[(size_t)code * ND + d], zev);
    }
}

// ---------------- EMA epilogue ---------------------------------------------------
__global__ void ema1_kernel(const float* __restrict__ ecs, float* __restrict__ necs)
{
    __shared__ float red[1024];
    int k = threadIdx.x;
    float ne = ecs[k] * 0.99f + 0.01f * g_cnt[k];
    necs[k] = ne;
    g_cnt[k] = 0.f;
    red[k] = ne;
    __syncthreads();
    for (int off = 512; off; off >>= 1) {
        if (k < off) red[k] += red[k + off];
        __syncthreads();
    }
    if (k == 0) g_n = red[0];
}

__global__ void ema2_kernel(const float* __restrict__ ema_w, const float* __restrict__ necs,
                            float* __restrict__ ncb)
{
    int k = blockIdx.x, d = threadIdx.x;
    float n = g_n;
    float smoothed = (necs[k] + 1e-5f) / (n + 1024.f * 1e-5f) * n;
    size_t idx = (size_t)k * ND + d;
    float nw = ema_w[idx] * 0.99f + 0.01f * g_sumcur[idx];
    ncb[idx] = nw / smoothed;
    g_sumcur[idx] = 0.f;
}

// ---------------- host launcher ---------------------------------------------------
extern "C" void kernel_launch(void* const* d_in, const int* in_sizes, int n_in,
                              void* d_out, int out_size)
{
    const float* X = (const float*)d_in[0];
    const float *W[6], *Bi[6], *G[5], *Be[5];

    bool sig = (in_sizes[3] == 256);
    if (!sig) {
        for (int i = 0; i < 6; i++) { W[i] = (const float*)d_in[1 + 2 * i]; Bi[i] = (const float*)d_in[2 + 2 * i]; }
        for (int i = 0; i < 5; i++) { G[i] = (const float*)d_in[13 + 2 * i]; Be[i] = (const float*)d_in[14 + 2 * i]; }
    } else {
        for (int i = 0; i < 5; i++) {
            W[i]  = (const float*)d_in[1 + 4 * i];
            Bi[i] = (const float*)d_in[2 + 4 * i];
            G[i]  = (const float*)d_in[3 + 4 * i];
            Be[i] = (const float*)d_in[4 + 4 * i];
        }
        W[5] = (const float*)d_in[21];
        Bi[5] = (const float*)d_in[22];
    }
    const float* codebook = (const float*)d_in[23];
    const float* ema_w    = (const float*)d_in[24];
    const float* ecs      = (const float*)d_in[25];

    float* out  = (float*)d_out;
    float* ze   = out;
    float* zq   = out + (size_t)33554432;
    float* ncb  = out + (size_t)67108864;
    float* necs = out + (size_t)67371008;

    float *bufA = nullptr, *bufB = nullptr;
    cudaGetSymbolAddress((void**)&bufA, g_bufA);
    cudaGetSymbolAddress((void**)&bufB, g_bufB);

    cudaFuncSetAttribute(convmma_kernel, cudaFuncAttributeMaxDynamicSharedMemorySize, SMEM_MMA);

    dim3 blk(256);
    conv1_kernel<<<dim3(65, 4, 32), blk>>>(X, W[0], Bi[0], bufA);
    scaleshift_kernel<<<1, 256>>>(G[0], Be[0], (double)(32.0 * 4097.0));
    wsplit_kernel<<<256, 256>>>(W[1]);
    convmma_kernel<<<dim3(64, 2, 32), blk, SMEM_MMA>>>(bufA, Bi[1], bufB, 4097, 4096, 1, TS_INT, 1);
    scaleshift_kernel<<<1, 256>>>(G[1], Be[1], (double)(32.0 * 4096.0));
    wsplit_kernel<<<256, 256>>>(W[2]);
    convmma_kernel<<<dim3(65, 2, 32), blk, SMEM_MMA>>>(bufB, Bi[2], bufA, 4096, 4097, 2, TS_INT, 1);
    scaleshift_kernel<<<1, 256>>>(G[2], Be[2], (double)(32.0 * 4097.0));
    wsplit_kernel<<<256, 256>>>(W[3]);
    convmma_kernel<<<dim3(64, 2, 32), blk, SMEM_MMA>>>(bufA, Bi[3], bufB, 4097, 4096, 1, TS_INT, 1);
    scaleshift_kernel<<<1, 256>>>(G[3], Be[3], (double)(32.0 * 4096.0));
    wsplit_kernel<<<256, 256>>>(W[4]);
    convmma_kernel<<<dim3(65, 2, 32), blk, SMEM_MMA>>>(bufB, Bi[4], bufA, 4096, 4097, 2, TS_INT, 1);
    scaleshift_kernel<<<1, 256>>>(G[4], Be[4], (double)(32.0 * 4097.0));
    wsplit_kernel<<<256, 256>>>(W[5]);
    convmma_kernel<<<dim3(64, 2, 32), blk, SMEM_MMA>>>(bufA, Bi[5], ze, 4097, 4096, 1, 4096, 0);

    cnorm_kernel<<<128, 256>>>(codebook);
    vq_kernel<<<2048, 256>>>(ze, codebook, zq);
    ema1_kernel<<<1, 1024>>>(ecs, necs);
    ema2_kernel<<<1024, 256>>>(ema_w, necs, ncb);
}

// round 11
// speedup vs baseline: 1.9892x; 1.0880x over previous
#include <cuda_runtime.h>
#include <cstdint>

#define NB 32
#define NT 4096
#define ND 256
#define NK 1024
#define TS_INT 4104        // token stride of intermediate activation buffers

// ---------------- scratch (static device globals; no allocation) ----------------
__device__ float  g_bufA[(size_t)NB * TS_INT * ND];
__device__ float  g_bufB[(size_t)NB * TS_INT * ND];
__device__ float  g_whi[(size_t)ND * 1024];     // weights (conv) / codebook hi (vq)
__device__ float  g_wlo[(size_t)ND * 1024];
__device__ double g_sum[ND];
__device__ double g_sumsq[ND];
__device__ float  g_scale[ND];
__device__ float  g_shift[ND];
__device__ float  g_cnorm[NK];
__device__ float  g_cnt[NK];
__device__ float  g_sumcur[(size_t)NK * ND];
__device__ float  g_n;
__device__ int    g_ids[(size_t)NB * NT];

// ---------------- helpers --------------------------------------------------------
__device__ __forceinline__ uint32_t smem_u32(const void* p) {
    uint32_t a;
    asm("{ .reg .u64 t; cvta.to.shared.u64 t, %1; cvt.u32.u64 %0, t; }" : "=r"(a) : "l"(p));
    return a;
}
__device__ __forceinline__ float tf32r(float x) {
    float r;
    asm("cvt.rna.tf32.f32 %0, %1;" : "=f"(r) : "f"(x));
    return r;
}
__device__ __forceinline__ uint32_t swz(uint32_t off) { return off ^ ((off >> 3) & 0x70); }

__device__ __forceinline__ void ldm_x4(uint32_t& r0, uint32_t& r1, uint32_t& r2, uint32_t& r3, uint32_t a) {
    asm volatile("ldmatrix.sync.aligned.m8n8.x4.shared.b16 {%0,%1,%2,%3}, [%4];"
                 : "=r"(r0), "=r"(r1), "=r"(r2), "=r"(r3) : "r"(a));
}
__device__ __forceinline__ void mma8(float* c, const uint32_t* a, const uint32_t* b) {
    asm volatile("mma.sync.aligned.m16n8k8.row.col.f32.tf32.tf32.f32 "
        "{%0,%1,%2,%3}, {%4,%5,%6,%7}, {%8,%9}, {%0,%1,%2,%3};"
        : "+f"(c[0]), "+f"(c[1]), "+f"(c[2]), "+f"(c[3])
        : "r"(a[0]), "r"(a[1]), "r"(a[2]), "r"(a[3]), "r"(b[0]), "r"(b[1]));
}
#define CP_ASYNC16(dst, src) asm volatile("cp.async.cg.shared.global [%0], [%1], 16;" :: "r"(dst), "l"(src))
#define CP_COMMIT()  asm volatile("cp.async.commit_group;" ::: "memory")
#define CP_WAIT0()   asm volatile("cp.async.wait_group 0;" ::: "memory")

// order-preserving float -> u32 map (finite inputs)
__device__ __forceinline__ uint32_t fbits_ord(float f) {
    uint32_t u = __float_as_uint(f);
    return (u & 0x80000000u) ? ~u : (u | 0x80000000u);
}

// conv smem stage: A_hi[128 rows x 128B] | A_lo | B_hi[72 rows x 32B] | B_lo
#define O_ALO 16384
#define O_BHI 32768
#define O_BLO (32768 + 2304)
#define STAGE 37888
#define O_STAT (2 * STAGE)
#define SMEM_MMA (O_STAT + 2048)

// vq smem: z-cache hi[8 chunks][64 rows x 128B] (64KB) | z lo (64KB) | 2 B stages | red
#define VQ_ZLO 65536
#define VQ_B   131072
#define VQ_BST 16384                         // per stage: cb hi 8KB + cb lo 8KB
#define VQ_RED (131072 + 2 * VQ_BST)
#define SMEM_VQ (VQ_RED + 2048)

// ---------------- weight split + permute prep (per conv layer) ------------------
__global__ void wsplit_kernel(const float* __restrict__ w)
{
    int i = blockIdx.x * 256 + threadIdx.x;      // 65536 = (oc, ch)
    int oc = i >> 8, ch = i & 255;
    float4 v = *(const float4*)&w[(size_t)oc * 1024 + ch * 4];
    size_t base = (size_t)oc * 1024 + (ch >> 3) * 32 + (ch & 7);
#pragma unroll
    for (int kk = 0; kk < 4; kk++) {
        float x = (&v.x)[kk];
        float hi = tf32r(x);
        g_whi[base + kk * 8] = hi;
        g_wlo[base + kk * 8] = tf32r(x - hi);
    }
}

// ---------------- plain hi/lo splits for VQ (z and codebook, row-major) ---------
__global__ void zsplit_kernel(const float* __restrict__ ze)
{
    size_t i = (size_t)blockIdx.x * 256 + threadIdx.x;   // float4 index
    float4 v = ((const float4*)ze)[i];
    float4 hi, lo;
    hi.x = tf32r(v.x); lo.x = tf32r(v.x - hi.x);
    hi.y = tf32r(v.y); lo.y = tf32r(v.y - hi.y);
    hi.z = tf32r(v.z); lo.z = tf32r(v.z - hi.z);
    hi.w = tf32r(v.w); lo.w = tf32r(v.w - hi.w);
    ((float4*)g_bufA)[i] = hi;
    ((float4*)g_bufB)[i] = lo;
}

__global__ void csplit_kernel(const float* __restrict__ cb)
{
    size_t i = (size_t)blockIdx.x * 256 + threadIdx.x;   // float4 index, 65536 total
    float4 v = ((const float4*)cb)[i];
    float4 hi, lo;
    hi.x = tf32r(v.x); lo.x = tf32r(v.x - hi.x);
    hi.y = tf32r(v.y); lo.y = tf32r(v.y - hi.y);
    hi.z = tf32r(v.z); lo.z = tf32r(v.z - hi.z);
    hi.w = tf32r(v.w); lo.w = tf32r(v.w - hi.w);
    ((float4*)g_whi)[i] = hi;
    ((float4*)g_wlo)[i] = lo;
}

// ============ conv D->D: mma.sync tf32 3x-split, 2 CTAs/SM (round-9, unchanged) ==
__global__ __launch_bounds__(256, 2) void convmma_kernel(
    const float* __restrict__ in, const float* __restrict__ bias,
    float* __restrict__ out, int Lin, int Lout, int pad, int tstride, int do_stats)
{
    extern __shared__ __align__(1024) char smem[];
    const int tid = threadIdx.x;
    const int wid = tid >> 5, lane = tid & 31;
    const int b = blockIdx.z, oc0 = blockIdx.y * 128, t0 = blockIdx.x * 64;
    const int ocw = (wid & 3) * 32;
    const int tokw = (wid >> 2) * 32;

    const uint32_t sb = smem_u32(smem);
    const float* xb = in + (size_t)b * TS_INT * ND;

    uint32_t abase[2];
    {
        int ar = ocw + (lane & 7) + ((lane >> 3) & 1) * 8;
        int aq = (lane >> 4) & 1;
#pragma unroll
        for (int mt = 0; mt < 2; mt++) {
            int r = ar + mt * 16;
            abase[mt] = (uint32_t)(r * 128 + ((aq * 16) ^ ((r & 7) << 4)));
        }
    }
    const int brow0 = tokw + (lane & 7) + (((lane >> 4) & 1) << 3);
    const uint32_t bcol = (uint32_t)(((lane >> 3) & 1) << 4);

    float C[2][4][4];
#pragma unroll
    for (int mt = 0; mt < 2; mt++)
#pragma unroll
        for (int nt = 0; nt < 4; nt++)
#pragma unroll
            for (int q = 0; q < 4; q++) C[mt][nt][q] = 0.f;

    const int jj = tid >> 1, hh = tid & 1;
    const bool bact = (tid < 134);
    float4 bpre0, spre, hpre;

    {
        const float* whp = g_whi + (size_t)oc0 * 1024;
        const float* wlp = g_wlo + (size_t)oc0 * 1024;
#pragma unroll
        for (int it = 0; it < 8; it++) {
            int idx = tid + it * 256, r = idx >> 3, ql = idx & 7, rr = r & 127;
            const float* src = ((r < 128) ? whp : wlp) + (size_t)rr * 1024 + ql * 4;
            uint32_t dst = sb + ((r < 128) ? 0u : (uint32_t)O_ALO) + swz((uint32_t)(rr * 128 + ql * 16));
            CP_ASYNC16(dst, src);
        }
        CP_COMMIT();
        if (bact) {
            int ti = t0 - pad + jj;
            bpre0 = ((unsigned)ti < (unsigned)Lin) ? *(const float4*)&xb[(size_t)ti * ND + hh * 4]
                                                   : make_float4(0.f, 0.f, 0.f, 0.f);
            spre = *(const float4*)&g_scale[hh * 4];
            hpre = *(const float4*)&g_shift[hh * 4];
        }
    }

    for (int cc = 0; cc < 32; cc++) {
        const uint32_t su = sb + (cc & 1) * STAGE;
        char* st = smem + (cc & 1) * STAGE;

        CP_WAIT0();
        if (bact) {
            int ti = t0 - pad + jj;
            bool ok = (unsigned)ti < (unsigned)Lin;
            float4 hi4, lo4;
#pragma unroll
            for (int q = 0; q < 4; q++) {
                float v = ok ? fmaxf(fmaf((&bpre0.x)[q], (&spre.x)[q], (&hpre.x)[q]), 0.f) : 0.f;
                float h = tf32r(v);
                (&hi4.x)[q] = h; (&lo4.x)[q] = tf32r(v - h);
            }
            uint32_t byte = (uint32_t)(jj * 32 + hh * 16) ^ ((uint32_t)(jj & 4) << 2);
            *(float4*)(st + O_BHI + byte) = hi4;
            *(float4*)(st + O_BLO + byte) = lo4;
        }
        __syncthreads();

        if (cc + 1 < 32) {
            const float* whp = g_whi + (size_t)oc0 * 1024 + (cc + 1) * 32;
            const float* wlp = g_wlo + (size_t)oc0 * 1024 + (cc + 1) * 32;
            uint32_t sd = sb + ((cc + 1) & 1) * STAGE;
#pragma unroll
            for (int it = 0; it < 8; it++) {
                int idx = tid + it * 256, r = idx >> 3, ql = idx & 7, rr = r & 127;
                const float* src = ((r < 128) ? whp : wlp) + (size_t)rr * 1024 + ql * 4;
                uint32_t dst = sd + ((r < 128) ? 0u : (uint32_t)O_ALO) + swz((uint32_t)(rr * 128 + ql * 16));
                CP_ASYNC16(dst, src);
            }
            CP_COMMIT();
            if (bact) {
                const int ch0 = (cc + 1) * 8;
                int ti = t0 - pad + jj;
                bpre0 = ((unsigned)ti < (unsigned)Lin) ? *(const float4*)&xb[(size_t)ti * ND + ch0 + hh * 4]
                                                       : make_float4(0.f, 0.f, 0.f, 0.f);
                spre = *(const float4*)&g_scale[ch0 + hh * 4];
                hpre = *(const float4*)&g_shift[ch0 + hh * 4];
            }
        }

#pragma unroll
        for (int ks = 0; ks < 4; ks++) {
            uint32_t bh[4][2], bl[4][2], ah[2][4], al[2][4];
#pragma unroll
            for (int p = 0; p < 2; p++) {
                int r = brow0 + p * 16 + ks;
                uint32_t byte = ((uint32_t)(r * 32) + bcol) ^ ((uint32_t)(r & 4) << 2);
                uint32_t ad = su + O_BHI + byte;
                ldm_x4(bh[2 * p][0], bh[2 * p][1], bh[2 * p + 1][0], bh[2 * p + 1][1], ad);
                ldm_x4(bl[2 * p][0], bl[2 * p][1], bl[2 * p + 1][0], bl[2 * p + 1][1],
                       ad + (O_BLO - O_BHI));
            }
#pragma unroll
            for (int mt = 0; mt < 2; mt++) {
                uint32_t ad = su + (abase[mt] ^ (uint32_t)(ks << 5));
                ldm_x4(ah[mt][0], ah[mt][1], ah[mt][2], ah[mt][3], ad);
            }
#pragma unroll
            for (int mt = 0; mt < 2; mt++)
#pragma unroll
                for (int nt = 0; nt < 4; nt++) mma8(C[mt][nt], ah[mt], bh[nt]);
#pragma unroll
            for (int mt = 0; mt < 2; mt++)
#pragma unroll
                for (int nt = 0; nt < 4; nt++) mma8(C[mt][nt], ah[mt], bl[nt]);
#pragma unroll
            for (int mt = 0; mt < 2; mt++) {
                uint32_t ad = su + (abase[mt] ^ (uint32_t)(ks << 5)) + O_ALO;
                ldm_x4(al[mt][0], al[mt][1], al[mt][2], al[mt][3], ad);
            }
#pragma unroll
            for (int mt = 0; mt < 2; mt++)
#pragma unroll
                for (int nt = 0; nt < 4; nt++) mma8(C[mt][nt], al[mt], bh[nt]);
        }
    }
    __syncthreads();

    double* ssumS = (double*)(smem + O_STAT);
    double* ssqS  = (double*)(smem + O_STAT + 1024);
    if (tid < 128) { ssumS[tid] = 0.0; ssqS[tid] = 0.0; }
    float* eb = (float*)smem;                 // [64 tok][132 oc]
    __syncthreads();

#pragma unroll
    for (int mt = 0; mt < 2; mt++) {
#pragma unroll
        for (int h = 0; h < 2; h++) {
            int ocl = ocw + mt * 16 + (lane >> 2) + h * 8;
            float bv = bias[oc0 + ocl];
            double s = 0.0, q = 0.0;
#pragma unroll
            for (int nt = 0; nt < 4; nt++) {
#pragma unroll
                for (int p = 0; p < 2; p++) {
                    int n = tokw + nt * 8 + (lane & 3) * 2 + p;
                    float v = C[mt][nt][h * 2 + p] + bv;
                    eb[n * 132 + ocl] = v;
                    if (do_stats && (t0 + n < Lout)) { double d = (double)v; s += d; q += d * d; }
                }
            }
            if (do_stats) { atomicAdd(&ssumS[ocl], s); atomicAdd(&ssqS[ocl], q); }
        }
    }
    __syncthreads();

    for (int idx = tid; idx < 2048; idx += 256) {
        int r = idx >> 5, ql = idx & 31;
        if (t0 + r < Lout)
            *(float4*)&out[((size_t)b * tstride + t0 + r) * ND + oc0 + ql * 4] =
                *(float4*)&eb[r * 132 + ql * 4];
    }
    if (do_stats && tid < 128) {
        atomicAdd(&g_sum[oc0 + tid], ssumS[tid]);
        atomicAdd(&g_sumsq[oc0 + tid], ssqS[tid]);
    }
}

// ---------------- layer 1: conv 12 -> 256, k=4, pad=2 (scalar; tiny K) ----------
__global__ __launch_bounds__(256) void conv1_kernel(
    const float* __restrict__ x, const float* __restrict__ w,
    const float* __restrict__ bias, float* __restrict__ out)
{
    __shared__ float in_s[12][68];
    __shared__ float w_s[64][49];
    __shared__ float o_s[64][65];
    __shared__ double ssum[64], ssq[64];

    const int tid = threadIdx.x;
    const int b = blockIdx.z, oc0 = blockIdx.y * 64, t0 = blockIdx.x * 64;
    const int ocl = tid & 63, tg = tid >> 6, tbase = tg * 16;
    const int Lout = 4097;

    for (int idx = tid; idx < 12 * 67; idx += 256) {
        int j = idx / 12, c = idx - j * 12;
        int ip = t0 - 2 + j;
        in_s[c][j] = ((unsigned)ip < 4096u) ? x[((size_t)b * NT + ip) * 12 + c] : 0.f;
    }
    for (int idx = tid; idx < 64 * 48; idx += 256) {
        int oc = idx / 48, r = idx - oc * 48;
        w_s[oc][r] = w[(size_t)(oc0 + oc) * 48 + r];
    }
    __syncthreads();

    float acc[16];
#pragma unroll
    for (int u = 0; u < 16; u++) acc[u] = 0.f;
#pragma unroll
    for (int c = 0; c < 12; c++) {
        float v[19];
#pragma unroll
        for (int u = 0; u < 19; u++) v[u] = in_s[c][tbase + u];
        float w0 = w_s[ocl][c * 4 + 0], w1 = w_s[ocl][c * 4 + 1];
        float w2 = w_s[ocl][c * 4 + 2], w3 = w_s[ocl][c * 4 + 3];
#pragma unroll
        for (int u = 0; u < 16; u++)
            acc[u] = fmaf(w3, v[u + 3], fmaf(w2, v[u + 2], fmaf(w1, v[u + 1], fmaf(w0, v[u], acc[u]))));
    }
    const float bv = bias[oc0 + ocl];
#pragma unroll
    for (int u = 0; u < 16; u++) acc[u] += bv;

    {
        double s = 0.0, q = 0.0;
#pragma unroll
        for (int u = 0; u < 16; u++)
            if (t0 + tbase + u < Lout) { double a = (double)acc[u]; s += a; q += a * a; }
        __syncthreads();
        if (tid < 64) { ssum[tid] = 0.0; ssq[tid] = 0.0; }
        __syncthreads();
        atomicAdd(&ssum[ocl], s);
        atomicAdd(&ssq[ocl], q);
        __syncthreads();
        if (tid < 64) {
            atomicAdd(&g_sum[oc0 + tid], ssum[tid]);
            atomicAdd(&g_sumsq[oc0 + tid], ssq[tid]);
        }
    }

    __syncthreads();
#pragma unroll
    for (int u = 0; u < 16; u++) o_s[ocl][tbase + u] = acc[u];
    __syncthreads();
    float* ob = out + ((size_t)b * TS_INT + t0) * ND + oc0;
    for (int idx = tid; idx < 4096; idx += 256) {
        int t = idx >> 6, oc = idx & 63;
        if (t0 + t < Lout) ob[(size_t)t * ND + oc] = o_s[oc][t];
    }
}

// ---------------- BN stats -> scale/shift for next layer; resets stats ----------
__global__ void scaleshift_kernel(const float* __restrict__ g, const float* __restrict__ be, double N)
{
    int c = threadIdx.x;
    double m = g_sum[c] / N;
    double var = g_sumsq[c] / N - m * m;
    double r = 1.0 / sqrt(var + 1e-5);
    double sc = (double)g[c] * r;
    g_scale[c] = (float)sc;
    g_shift[c] = (float)((double)be[c] - m * sc);
    g_sum[c] = 0.0;
    g_sumsq[c] = 0.0;
}

// ---------------- ||codebook_k||^2 (exact fp32) ---------------------------------
__global__ void cnorm_kernel(const float* __restrict__ cb)
{
    int gw = (blockIdx.x * 256 + threadIdx.x) >> 5;
    int lane = threadIdx.x & 31;
    float s = 0.f;
    const float* row = cb + (size_t)gw * ND;
    for (int d = lane; d < ND; d += 32) { float v = row[d]; s = fmaf(v, v, s); }
#pragma unroll
    for (int off = 16; off; off >>= 1) s += __shfl_xor_sync(0xffffffffu, s, off);
    if (lane == 0) g_cnorm[gw] = s;
}

// ============ VQ argmin as mma.sync tf32 3x-split GEMM ==========================
// CTA: 64 tokens x all 1024 codes (16 code-tiles of 64). z tile (K=256, hi+lo)
// cached in smem; codebook tiles streamed via cp.async double buffer.
// Warp layout: 2 tok-warps x 4 code-warps; warp tile 32 tok x 16 codes.
__global__ __launch_bounds__(256, 1) void vqmma_kernel(int* __restrict__ ids)
{
    extern __shared__ __align__(1024) char smem[];
    const int tid = threadIdx.x;
    const int wid = tid >> 5, lane = tid & 31;
    const int tok0 = blockIdx.x * 64;
    const int tokw = (wid >> 2) * 32;
    const int cw = (wid & 3) * 16;

    const uint32_t sb = smem_u32(smem);

    // ---- load z cache: 2 halves x 8 chunks x 64 rows x 8 float4 = 8192 loads ---
    {
        const float* zhi = g_bufA;
        const float* zlo = g_bufB;
#pragma unroll
        for (int it = 0; it < 32; it++) {
            int idx = tid + it * 256;
            int q = idx & 7, r = (idx >> 3) & 63, kc = (idx >> 9) & 7, half = idx >> 12;
            const float* src = (half ? zlo : zhi) + ((size_t)(tok0 + r) * 256 + kc * 32 + q * 4);
            uint32_t dst = sb + half * VQ_ZLO + kc * 8192 + swz((uint32_t)(r * 128 + q * 16));
            CP_ASYNC16(dst, src);
        }
        CP_COMMIT();
    }
    // ---- prefetch codebook stage 0 (ct=0, kc=0) --------------------------------
    {
#pragma unroll
        for (int it = 0; it < 4; it++) {
            int idx = tid + it * 256;
            int q = idx & 7, r = (idx >> 3) & 63, half = idx >> 9;
            const float* src = (half ? g_wlo : g_whi) + ((size_t)r * 256 + q * 4);
            uint32_t dst = sb + VQ_B + half * 8192 + swz((uint32_t)(r * 128 + q * 16));
            CP_ASYNC16(dst, src);
        }
        CP_COMMIT();
    }

    // A (z) fragment bases
    uint32_t abase[2];
    {
        int ar = tokw + (lane & 7) + ((lane >> 3) & 1) * 8;
        int aq = (lane >> 4) & 1;
#pragma unroll
        for (int mt = 0; mt < 2; mt++) {
            int r = ar + mt * 16;
            abase[mt] = (uint32_t)(r * 128 + ((aq * 16) ^ ((r & 7) << 4)));
        }
    }
    // B (codebook) paired-x4 base
    const int brow = cw + (lane & 7) + (((lane >> 4) & 1) << 3);
    const uint32_t bcol = (uint32_t)(((lane >> 3) & 1) << 4);

    unsigned long long best[4];
#pragma unroll
    for (int i = 0; i < 4; i++) best[i] = ~0ull;

    float C[2][2][4];

    for (int s = 0; s < 128; s++) {
        const int ct = s >> 3, kc = s & 7;
        const uint32_t bst = sb + VQ_B + (s & 1) * VQ_BST;

        CP_WAIT0();
        __syncthreads();

        // prefetch next stage
        if (s + 1 < 128) {
            const int nct = (s + 1) >> 3, nkc = (s + 1) & 7;
            uint32_t sd = sb + VQ_B + ((s + 1) & 1) * VQ_BST;
#pragma unroll
            for (int it = 0; it < 4; it++) {
                int idx = tid + it * 256;
                int q = idx & 7, r = (idx >> 3) & 63, half = idx >> 9;
                const float* src = (half ? g_wlo : g_whi) + ((size_t)(nct * 64 + r) * 256 + nkc * 32 + q * 4);
                uint32_t dst = sd + half * 8192 + swz((uint32_t)(r * 128 + q * 16));
                CP_ASYNC16(dst, src);
            }
            CP_COMMIT();
        }

        if (kc == 0) {
#pragma unroll
            for (int mt = 0; mt < 2; mt++)
#pragma unroll
                for (int nt = 0; nt < 2; nt++)
#pragma unroll
                    for (int q = 0; q < 4; q++) C[mt][nt][q] = 0.f;
        }

        const uint32_t za = sb + kc * 8192;
#pragma unroll
        for (int ks = 0; ks < 4; ks++) {
            uint32_t bh[2][2], bl[2][2], ah[2][4], al[2][4];
            {
                uint32_t byte = (uint32_t)(brow * 128) + (((uint32_t)(ks * 32) + bcol) ^ ((uint32_t)(brow & 7) << 4));
                uint32_t ad = bst + byte;
                ldm_x4(bh[0][0], bh[0][1], bh[1][0], bh[1][1], ad);
                ldm_x4(bl[0][0], bl[0][1], bl[1][0], bl[1][1], ad + 8192);
            }
#pragma unroll
            for (int mt = 0; mt < 2; mt++) {
                uint32_t ad = za + (abase[mt] ^ (uint32_t)(ks << 5));
                ldm_x4(ah[mt][0], ah[mt][1], ah[mt][2], ah[mt][3], ad);
            }
#pragma unroll
            for (int mt = 0; mt < 2; mt++)
#pragma unroll
                for (int nt = 0; nt < 2; nt++) mma8(C[mt][nt], ah[mt], bh[nt]);
#pragma unroll
            for (int mt = 0; mt < 2; mt++)
#pragma unroll
                for (int nt = 0; nt < 2; nt++) mma8(C[mt][nt], ah[mt], bl[nt]);
#pragma unroll
            for (int mt = 0; mt < 2; mt++) {
                uint32_t ad = za + VQ_ZLO + (abase[mt] ^ (uint32_t)(ks << 5));
                ldm_x4(al[mt][0], al[mt][1], al[mt][2], al[mt][3], ad);
            }
#pragma unroll
            for (int mt = 0; mt < 2; mt++)
#pragma unroll
                for (int nt = 0; nt < 2; nt++) mma8(C[mt][nt], al[mt], bh[nt]);
        }

        // per-code-tile argmin update (codes ascending within each thread)
        if (kc == 7) {
#pragma unroll
            for (int mt = 0; mt < 2; mt++)
#pragma unroll
                for (int h = 0; h < 2; h++) {
#pragma unroll
                    for (int nt = 0; nt < 2; nt++)
#pragma unroll
                        for (int p = 0; p < 2; p++) {
                            int code = ct * 64 + cw + nt * 8 + (lane & 3) * 2 + p;
                            float dist = fmaf(-2.f, C[mt][nt][h * 2 + p], g_cnorm[code]);
                            unsigned long long cand =
                                ((unsigned long long)fbits_ord(dist) << 32) | (unsigned)code;
                            unsigned long long* bp = &best[mt * 2 + h];
                            if (cand < *bp) *bp = cand;
                        }
                }
        }
    }

    // reduce over the 4 lanes (lane&3) sharing each token row
#pragma unroll
    for (int off = 1; off <= 2; off <<= 1) {
#pragma unroll
        for (int i = 0; i < 4; i++) {
            unsigned long long o = __shfl_xor_sync(0xffffffffu, best[i], off);
            if (o < best[i]) best[i] = o;
        }
    }
    unsigned long long* red = (unsigned long long*)(smem + VQ_RED);   // [64][4]
    __syncthreads();
    if ((lane & 3) == 0) {
#pragma unroll
        for (int mt = 0; mt < 2; mt++)
#pragma unroll
            for (int h = 0; h < 2; h++) {
                int trow = tokw + mt * 16 + h * 8 + (lane >> 2);
                red[trow * 4 + (wid & 3)] = best[mt * 2 + h];
            }
    }
    __syncthreads();
    if (tid < 64) {
        unsigned long long m = red[tid * 4];
#pragma unroll
        for (int i = 1; i < 4; i++) { unsigned long long o = red[tid * 4 + i]; if (o < m) m = o; }
        ids[tok0 + tid] = (int)(m & 0xFFFFFFFFu);
    }
}

// ---------------- VQ tail: counts + z_q + segment sums --------------------------
__global__ __launch_bounds__(256) void vqtail_kernel(
    const float* __restrict__ ze, const float* __restrict__ cb, float* __restrict__ zq)
{
    __shared__ int sid[64];
    const int tid = threadIdx.x;
    const int tok0 = blockIdx.x * 64;
    if (tid < 64) sid[tid] = g_ids[tok0 + tid];
    __syncthreads();
    if (tid < 64) atomicAdd(&g_cnt[sid[tid]], 1.0f);
    for (int e = tid; e < 64 * ND; e += 256) {
        int r = e >> 8, d = e & 255;
        int code = sid[r];
        size_t gz = (size_t)(tok0 + r) * ND + d;
        float zev = ze[gz];
        float cbv = cb[(size_t)code * ND + d];
        zq[gz] = zev + (cbv - zev);
        atomicAdd(&g_sumcur[(size_t)code * ND + d], zev);
    }
}

// ---------------- EMA epilogue ---------------------------------------------------
__global__ void ema1_kernel(const float* __restrict__ ecs, float* __restrict__ necs)
{
    __shared__ float red[1024];
    int k = threadIdx.x;
    float ne = ecs[k] * 0.99f + 0.01f * g_cnt[k];
    necs[k] = ne;
    g_cnt[k] = 0.f;
    red[k] = ne;
    __syncthreads();
    for (int off = 512; off; off >>= 1) {
        if (k < off) red[k] += red[k + off];
        __syncthreads();
    }
    if (k == 0) g_n = red[0];
}

__global__ void ema2_kernel(const float* __restrict__ ema_w, const float* __restrict__ necs,
                            float* __restrict__ ncb)
{
    int k = blockIdx.x, d = threadIdx.x;
    float n = g_n;
    float smoothed = (necs[k] + 1e-5f) / (n + 1024.f * 1e-5f) * n;
    size_t idx = (size_t)k * ND + d;
    float nw = ema_w[idx] * 0.99f + 0.01f * g_sumcur[idx];
    ncb[idx] = nw / smoothed;
    g_sumcur[idx] = 0.f;
}

// ---------------- host launcher ---------------------------------------------------
extern "C" void kernel_launch(void* const* d_in, const int* in_sizes, int n_in,
                              void* d_out, int out_size)
{
    const float* X = (const float*)d_in[0];
    const float *W[6], *Bi[6], *G[5], *Be[5];

    bool sig = (in_sizes[3] == 256);
    if (!sig) {
        for (int i = 0; i < 6; i++) { W[i] = (const float*)d_in[1 + 2 * i]; Bi[i] = (const float*)d_in[2 + 2 * i]; }
        for (int i = 0; i < 5; i++) { G[i] = (const float*)d_in[13 + 2 * i]; Be[i] = (const float*)d_in[14 + 2 * i]; }
    } else {
        for (int i = 0; i < 5; i++) {
            W[i]  = (const float*)d_in[1 + 4 * i];
            Bi[i] = (const float*)d_in[2 + 4 * i];
            G[i]  = (const float*)d_in[3 + 4 * i];
            Be[i] = (const float*)d_in[4 + 4 * i];
        }
        W[5] = (const float*)d_in[21];
        Bi[5] = (const float*)d_in[22];
    }
    const float* codebook = (const float*)d_in[23];
    const float* ema_w    = (const float*)d_in[24];
    const float* ecs      = (const float*)d_in[25];

    float* out  = (float*)d_out;
    float* ze   = out;
    float* zq   = out + (size_t)33554432;
    float* ncb  = out + (size_t)67108864;
    float* necs = out + (size_t)67371008;

    float *bufA = nullptr, *bufB = nullptr;
    cudaGetSymbolAddress((void**)&bufA, g_bufA);
    cudaGetSymbolAddress((void**)&bufB, g_bufB);
    int* idsp = nullptr;
    cudaGetSymbolAddress((void**)&idsp, g_ids);

    cudaFuncSetAttribute(convmma_kernel, cudaFuncAttributeMaxDynamicSharedMemorySize, SMEM_MMA);
    cudaFuncSetAttribute(vqmma_kernel, cudaFuncAttributeMaxDynamicSharedMemorySize, SMEM_VQ);

    dim3 blk(256);
    conv1_kernel<<<dim3(65, 4, 32), blk>>>(X, W[0], Bi[0], bufA);
    scaleshift_kernel<<<1, 256>>>(G[0], Be[0], (double)(32.0 * 4097.0));
    wsplit_kernel<<<256, 256>>>(W[1]);
    convmma_kernel<<<dim3(64, 2, 32), blk, SMEM_MMA>>>(bufA, Bi[1], bufB, 4097, 4096, 1, TS_INT, 1);
    scaleshift_kernel<<<1, 256>>>(G[1], Be[1], (double)(32.0 * 4096.0));
    wsplit_kernel<<<256, 256>>>(W[2]);
    convmma_kernel<<<dim3(65, 2, 32), blk, SMEM_MMA>>>(bufB, Bi[2], bufA, 4096, 4097, 2, TS_INT, 1);
    scaleshift_kernel<<<1, 256>>>(G[2], Be[2], (double)(32.0 * 4097.0));
    wsplit_kernel<<<256, 256>>>(W[3]);
    convmma_kernel<<<dim3(64, 2, 32), blk, SMEM_MMA>>>(bufA, Bi[3], bufB, 4097, 4096, 1, TS_INT, 1);
    scaleshift_kernel<<<1, 256>>>(G[3], Be[3], (double)(32.0 * 4096.0));
    wsplit_kernel<<<256, 256>>>(W[4]);
    convmma_kernel<<<dim3(65, 2, 32), blk, SMEM_MMA>>>(bufB, Bi[4], bufA, 4096, 4097, 2, TS_INT, 1);
    scaleshift_kernel<<<1, 256>>>(G[4], Be[4], (double)(32.0 * 4097.0));
    wsplit_kernel<<<256, 256>>>(W[5]);
    convmma_kernel<<<dim3(64, 2, 32), blk, SMEM_MMA>>>(bufA, Bi[5], ze, 4097, 4096, 1, 4096, 0);

    // VQ: split z (reusing bufA/bufB) + codebook, tensor argmin, tail epilogue
    zsplit_kernel<<<32768, 256>>>(ze);
    csplit_kernel<<<256, 256>>>(codebook);
    cnorm_kernel<<<128, 256>>>(codebook);
    vqmma_kernel<<<2048, 256, SMEM_VQ>>>(idsp);
    vqtail_kernel<<<2048, 256>>>(ze, codebook, zq);
    ema1_kernel<<<1, 1024>>>(ecs, necs);
    ema2_kernel<<<1024, 256>>>(ema_w, necs, ncb);
}